// round 7
// baseline (speedup 1.0000x reference)
#include <cuda_runtime.h>
#include <cuda_bf16.h>
#include <math.h>
#include <cstdint>

// ---------------- problem constants ----------------
#define NUM_SUBNETS 8
#define REGIONS     50
#define TOTAL_R     400
#define HIDDEN      512
#define HEADS       8
#define HEAD_DIM    64
#define BATCH       256
#define FLAT        2500
#define ROWS        (NUM_SUBNETS * BATCH)   // 2048
#define LN_EPS      1e-5f
#define KPAD1       2560                    // FLAT padded to multiple of 64

// GEMM tiling
#define BM 64
#define BN 64
#define BK 64
#define ASTRIDE 144                         // bytes per 64-col bf16 row (128 + 16 pad)
#define T_BYTES (BM * ASTRIDE)              // 9216 per tile array
#define STAGE   (4 * T_BYTES)               // 36864 (Ahi,Alo,Bhi,Blo)
#define NSTAGE  3
#define GEMM_SMEM (NSTAGE * STAGE)          // 110592 -> 2 CTAs/SM

typedef unsigned long long u64;

// ---------------- scratch (device globals) ----------------
__device__ __nv_bfloat16 g_flat_hi[ROWS * KPAD1];
__device__ __nv_bfloat16 g_flat_lo[ROWS * KPAD1];
__device__ __nv_bfloat16 g_W1T_hi[NUM_SUBNETS * HIDDEN * KPAD1];
__device__ __nv_bfloat16 g_W1T_lo[NUM_SUBNETS * HIDDEN * KPAD1];
__device__ __nv_bfloat16 g_W2T_hi[NUM_SUBNETS * HIDDEN * HIDDEN];
__device__ __nv_bfloat16 g_W2T_lo[NUM_SUBNETS * HIDDEN * HIDDEN];
__device__ __nv_bfloat16 g_WqkvT_hi[3 * HIDDEN * HIDDEN];
__device__ __nv_bfloat16 g_WqkvT_lo[3 * HIDDEN * HIDDEN];
__device__ __nv_bfloat16 g_WoT_hi[HIDDEN * HIDDEN];
__device__ __nv_bfloat16 g_WoT_lo[HIDDEN * HIDDEN];
__device__ __nv_bfloat16 g_WpT_hi[HIDDEN * HIDDEN];
__device__ __nv_bfloat16 g_WpT_lo[HIDDEN * HIDDEN];

__device__ float         g_part[2 * ROWS * HIDDEN];   // split-K partial sums
__device__ __nv_bfloat16 g_h_hi[ROWS * HIDDEN];
__device__ __nv_bfloat16 g_h_lo[ROWS * HIDDEN];
__device__ float         g_xsub[ROWS * HIDDEN];
__device__ __nv_bfloat16 g_xn_hi[ROWS * HIDDEN];
__device__ __nv_bfloat16 g_xn_lo[ROWS * HIDDEN];
__device__ float         g_q[ROWS * HIDDEN];
__device__ float         g_k[ROWS * HIDDEN];
__device__ float         g_v[ROWS * HIDDEN];
__device__ __nv_bfloat16 g_ctx_hi[ROWS * HIDDEN];
__device__ __nv_bfloat16 g_ctx_lo[ROWS * HIDDEN];
__device__ __nv_bfloat16 g_t_hi[ROWS * HIDDEN];
__device__ __nv_bfloat16 g_t_lo[ROWS * HIDDEN];

// ---------------- PTX helpers (sm_80-ratified only) ----------------
__device__ __forceinline__ uint32_t smem_u32(const void* p) {
    uint32_t a;
    asm("{ .reg .u64 t; cvta.to.shared.u64 t, %1; cvt.u32.u64 %0, t; }" : "=r"(a) : "l"(p));
    return a;
}
__device__ __forceinline__ void cpa16(uint32_t s, const void* g) {
    asm volatile("cp.async.cg.shared.global [%0], [%1], 16;" :: "r"(s), "l"(g));
}
__device__ __forceinline__ void cpa_commit() {
    asm volatile("cp.async.commit_group;" ::: "memory");
}
template<int N> __device__ __forceinline__ void cpa_wait() {
    asm volatile("cp.async.wait_group %0;" :: "n"(N) : "memory");
}
__device__ __forceinline__ void ldm4(uint32_t a, uint32_t* r) {
    asm volatile("ldmatrix.sync.aligned.m8n8.x4.shared.b16 {%0,%1,%2,%3}, [%4];"
        : "=r"(r[0]), "=r"(r[1]), "=r"(r[2]), "=r"(r[3]) : "r"(a));
}
__device__ __forceinline__ void mma16816(float* c, const uint32_t* a, uint32_t b0, uint32_t b1) {
    asm volatile("mma.sync.aligned.m16n8k16.row.col.f32.bf16.bf16.f32 "
        "{%0,%1,%2,%3},{%4,%5,%6,%7},{%8,%9},{%0,%1,%2,%3};"
        : "+f"(c[0]), "+f"(c[1]), "+f"(c[2]), "+f"(c[3])
        : "r"(a[0]), "r"(a[1]), "r"(a[2]), "r"(a[3]), "r"(b0), "r"(b1));
}

__device__ __forceinline__ void store_hilo(__nv_bfloat16* hi, __nv_bfloat16* lo,
                                           size_t off, float v0, float v1) {
    __nv_bfloat16 h0 = __float2bfloat16(v0);
    __nv_bfloat16 h1 = __float2bfloat16(v1);
    __nv_bfloat16 l0 = __float2bfloat16(v0 - __bfloat162float(h0));
    __nv_bfloat16 l1 = __float2bfloat16(v1 - __bfloat162float(h1));
    __nv_bfloat162 hp; hp.x = h0; hp.y = h1;
    __nv_bfloat162 lp; lp.x = l0; lp.y = l1;
    *(__nv_bfloat162*)(hi + off) = hp;
    *(__nv_bfloat162*)(lo + off) = lp;
}

union BF4 { uint2 u; __nv_bfloat162 p[2]; };

__device__ __forceinline__ void split4(const float* v, BF4& hv, BF4& lv) {
    __nv_bfloat16 h0 = __float2bfloat16(v[0]);
    __nv_bfloat16 h1 = __float2bfloat16(v[1]);
    __nv_bfloat16 h2 = __float2bfloat16(v[2]);
    __nv_bfloat16 h3 = __float2bfloat16(v[3]);
    hv.p[0].x = h0; hv.p[0].y = h1; hv.p[1].x = h2; hv.p[1].y = h3;
    lv.p[0].x = __float2bfloat16(v[0] - __bfloat162float(h0));
    lv.p[0].y = __float2bfloat16(v[1] - __bfloat162float(h1));
    lv.p[1].x = __float2bfloat16(v[2] - __bfloat162float(h2));
    lv.p[1].y = __float2bfloat16(v[3] - __bfloat162float(h3));
}

// ---------------- kernel: extract diagonal blocks -> bf16 hi/lo (4 elems/thread) ----------------
__global__ void extract_kernel(const float* __restrict__ x) {
    int q = blockIdx.x * blockDim.x + threadIdx.x;        // quad index
    if (q >= ROWS * KPAD1 / 4) return;
    int f0 = (q % (KPAD1 / 4)) * 4;
    int sb = q / (KPAD1 / 4);
    int b  = sb & (BATCH - 1);
    int s  = sb >> 8;
    const float* xb = x + (size_t)b * (TOTAL_R * TOTAL_R);
    float v[4];
    #pragma unroll
    for (int e = 0; e < 4; e++) {
        int f = f0 + e;
        float vv = 0.f;
        if (f < FLAT) {
            int i = f / REGIONS;
            int j = f - i * REGIONS;
            vv = xb[(s * REGIONS + i) * TOTAL_R + (s * REGIONS + j)];
        }
        v[e] = vv;
    }
    BF4 hv, lv; split4(v, hv, lv);
    size_t off = (size_t)sb * KPAD1 + f0;
    *(uint2*)(g_flat_hi + off) = hv.u;
    *(uint2*)(g_flat_lo + off) = lv.u;
}

// ---------------- W1 transpose+split: [s][2500][512] -> [s][512][2560] ----------------
__global__ void wconv_w1_kernel(const float* __restrict__ src) {
    __shared__ float tile[32][33];
    int k0 = blockIdx.x * 32, n0 = blockIdx.y * 32, z = blockIdx.z;
    const float* sp = src + (size_t)z * FLAT * HIDDEN;
    size_t dbase = (size_t)z * HIDDEN * KPAD1;
    int tid = threadIdx.x;
    int tx = tid & 31, ty = tid >> 5;       // 256 threads
    #pragma unroll
    for (int r = 0; r < 4; r++) {
        int k = k0 + ty + r * 8;
        tile[ty + r * 8][tx] = (k < FLAT) ? sp[(size_t)k * HIDDEN + n0 + tx] : 0.f;
    }
    __syncthreads();
    int n = tid >> 3, kq = (tid & 7) * 4;
    float v[4];
    #pragma unroll
    for (int i = 0; i < 4; i++) v[i] = tile[kq + i][n];
    BF4 hv, lv; split4(v, hv, lv);
    size_t off = dbase + (size_t)(n0 + n) * KPAD1 + k0 + kq;
    *(uint2*)(g_W1T_hi + off) = hv.u;
    *(uint2*)(g_W1T_lo + off) = lv.u;
}

// ---------------- batched 512x512 transpose+split (13 slices, one launch) ----------------
struct W13 {
    const float* src[13];
    __nv_bfloat16* dhi[13];
    __nv_bfloat16* dlo[13];
};
__global__ void wconv512_kernel(W13 a) {
    __shared__ float tile[32][33];
    int z = blockIdx.z;
    const float* sp = a.src[z];
    __nv_bfloat16* dhi = a.dhi[z];
    __nv_bfloat16* dlo = a.dlo[z];
    int k0 = blockIdx.x * 32, n0 = blockIdx.y * 32;
    int tid = threadIdx.x;
    int tx = tid & 31, ty = tid >> 5;
    #pragma unroll
    for (int r = 0; r < 4; r++) {
        int k = k0 + ty + r * 8;
        tile[ty + r * 8][tx] = sp[(size_t)k * HIDDEN + n0 + tx];
    }
    __syncthreads();
    int n = tid >> 3, kq = (tid & 7) * 4;
    float v[4];
    #pragma unroll
    for (int i = 0; i < 4; i++) v[i] = tile[kq + i][n];
    BF4 hv, lv; split4(v, hv, lv);
    size_t off = (size_t)(n0 + n) * HIDDEN + k0 + kq;
    *(uint2*)(dhi + off) = hv.u;
    *(uint2*)(dlo + off) = lv.u;
}

// ---------------- mma.sync GEMM: C[2048][N] = A[2048][K] * W^T + epilogue ----------------
// C = Ah*Bh + Ah*Bl + Al*Bh, fp32 accum. BM=BN=64, BK=64.
// 8 warps as (wm 2) x (wn 2) x (wk 2), warp tile 32x32, K split across wk,
// reduced through SMEM. MMAs ordered term-major: accumulator RAW distance = 8.
// blockIdx.z = CTA-level split-K slice (kOff = z*Ksteps*BK), partials for EP==5.
// EP: 0 relu->hi/lo | 1 f32 | 2 qkv split f32 | 3 hi/lo | 4 resid+permute f32 | 5 raw partial f32
template<int EP>
__global__ __launch_bounds__(256, 2) void tc_gemm(
    const __nv_bfloat16* __restrict__ Ahi, const __nv_bfloat16* __restrict__ Alo, int sA,
    const __nv_bfloat16* __restrict__ Bhi, const __nv_bfloat16* __restrict__ Blo, int sB,
    long bSub, int Ksteps,
    const float* __restrict__ bias,
    float* __restrict__ o32,
    __nv_bfloat16* __restrict__ oHi, __nv_bfloat16* __restrict__ oLo,
    const float* __restrict__ resid,
    float* __restrict__ oq, float* __restrict__ okk, float* __restrict__ ov,
    const float* __restrict__ bq, const float* __restrict__ bk, const float* __restrict__ bv)
{
    extern __shared__ __align__(128) char smem[];
    const uint32_t sbase = smem_u32(smem);
    const int tid = threadIdx.x;
    const int mBase = blockIdx.y * BM;
    const int nBase = blockIdx.x * BN;
    const int sIdx = blockIdx.y >> 2;        // 4 M-tiles (256 rows) per subnet
    const size_t kOff = (size_t)blockIdx.z * (size_t)Ksteps * BK;

    const __nv_bfloat16* aH = Ahi + (size_t)mBase * sA + kOff;
    const __nv_bfloat16* aL = Alo + (size_t)mBase * sA + kOff;
    size_t boff = (bSub > 0 ? (size_t)sIdx * (size_t)bSub : 0) + (size_t)nBase * sB + kOff;
    const __nv_bfloat16* bH = Bhi + boff;
    const __nv_bfloat16* bL = Blo + boff;
    const float* biasP = bias ? (bias + (bSub > 0 ? sIdx * HIDDEN : 0)) : bias;
    float* oPart = (EP == 5) ? (o32 + (size_t)blockIdx.z * (ROWS * HIDDEN)) : o32;

    // ---- async-copy one K-chunk; ALWAYS commits exactly one group ----
    auto issue = [&](int chunk) {
        if (chunk < Ksteps) {
            const uint32_t st = sbase + (chunk % NSTAGE) * STAGE;
            const int k0 = chunk * BK;
            #pragma unroll
            for (int i = 0; i < 2; i++) {
                int idx = tid + i * 256;
                int row = idx >> 3, c = idx & 7;
                uint32_t so = st + row * ASTRIDE + c * 16;
                cpa16(so,           aH + (size_t)row * sA + k0 + c * 8);
                cpa16(so + T_BYTES, aL + (size_t)row * sA + k0 + c * 8);
            }
            #pragma unroll
            for (int i = 0; i < 2; i++) {
                int idx = tid + i * 256;
                int row = idx >> 3, c = idx & 7;
                uint32_t so = st + 2 * T_BYTES + row * ASTRIDE + c * 16;
                cpa16(so,           bH + (size_t)row * sB + k0 + c * 8);
                cpa16(so + T_BYTES, bL + (size_t)row * sB + k0 + c * 8);
            }
        }
        cpa_commit();
    };

    issue(0); issue(1);

    const int wid = tid >> 5, lane = tid & 31;
    const int wk = wid >> 2;                 // 0/1 : handles kk = 2*wk + {0,1}
    const int wm = (wid >> 1) & 1;           // 32-row half
    const int wn = wid & 1;                  // 32-col half
    const uint32_t lrow = lane & 15;
    const uint32_t lcol = (lane >> 4) * 16;

    float acc[2][4][4];                      // [m16 tile][n8 tile][frag]
    #pragma unroll
    for (int i = 0; i < 2; i++)
        #pragma unroll
        for (int j = 0; j < 4; j++)
            #pragma unroll
            for (int t = 0; t < 4; t++) acc[i][j][t] = 0.f;

    for (int s = 0; s < Ksteps; ++s) {
        cpa_wait<1>();                 // stage s landed
        __syncthreads();               // all warps done with buffer (s-1)%3
        issue(s + 2);                  // refill freed buffer, overlaps compute
        const uint32_t st = sbase + (s % NSTAGE) * STAGE;
        #pragma unroll
        for (int j = 0; j < 2; ++j) {
            const int kk = wk * 2 + j;
            uint32_t aHf[2][4], aLf[2][4], bHf[2][4], bLf[2][4];
            #pragma unroll
            for (int am = 0; am < 2; am++) {
                uint32_t ad = st + (wm * 32 + am * 16 + lrow) * ASTRIDE + kk * 32 + lcol;
                ldm4(ad,           aHf[am]);
                ldm4(ad + T_BYTES, aLf[am]);
            }
            #pragma unroll
            for (int bt = 0; bt < 2; bt++) {
                uint32_t bd = st + 2 * T_BYTES + (wn * 32 + bt * 16 + lrow) * ASTRIDE + kk * 32 + lcol;
                ldm4(bd,           bHf[bt]);
                ldm4(bd + T_BYTES, bLf[bt]);
            }
            // term-major order: each accumulator reused only every 8 MMAs
            #pragma unroll
            for (int am = 0; am < 2; am++)
                #pragma unroll
                for (int bt = 0; bt < 2; bt++) {
                    mma16816(acc[am][2*bt],   aHf[am], bHf[bt][0], bHf[bt][2]);
                    mma16816(acc[am][2*bt+1], aHf[am], bHf[bt][1], bHf[bt][3]);
                }
            #pragma unroll
            for (int am = 0; am < 2; am++)
                #pragma unroll
                for (int bt = 0; bt < 2; bt++) {
                    mma16816(acc[am][2*bt],   aHf[am], bLf[bt][0], bLf[bt][2]);
                    mma16816(acc[am][2*bt+1], aHf[am], bLf[bt][1], bLf[bt][3]);
                }
            #pragma unroll
            for (int am = 0; am < 2; am++)
                #pragma unroll
                for (int bt = 0; bt < 2; bt++) {
                    mma16816(acc[am][2*bt],   aLf[am], bHf[bt][0], bHf[bt][2]);
                    mma16816(acc[am][2*bt+1], aLf[am], bHf[bt][1], bHf[bt][3]);
                }
        }
    }

    // ---- reduce wk=1 partial sums into wk=0 via SMEM (stages are dead now) ----
    __syncthreads();
    float* red = (float*)smem;               // 4 regions of [32][34] floats
    float* rbase = red + (wm * 2 + wn) * (32 * 34);
    if (wk == 1) {
        #pragma unroll
        for (int am = 0; am < 2; am++)
            #pragma unroll
            for (int an = 0; an < 4; an++)
                #pragma unroll
                for (int t = 0; t < 4; t++) {
                    int row = am * 16 + (lane >> 2) + (t >> 1) * 8;
                    int col = an * 8 + (lane & 3) * 2 + (t & 1);
                    rbase[row * 34 + col] = acc[am][an][t];
                }
    }
    __syncthreads();
    if (wk == 1) return;
    #pragma unroll
    for (int am = 0; am < 2; am++)
        #pragma unroll
        for (int an = 0; an < 4; an++)
            #pragma unroll
            for (int t = 0; t < 4; t++) {
                int row = am * 16 + (lane >> 2) + (t >> 1) * 8;
                int col = an * 8 + (lane & 3) * 2 + (t & 1);
                acc[am][an][t] += rbase[row * 34 + col];
            }

    // ---- epilogue (wk=0 warps only): registers -> global ----
    #pragma unroll
    for (int am = 0; am < 2; am++) {
        #pragma unroll
        for (int an = 0; an < 4; an++) {
            int m0 = mBase + wm * 32 + am * 16 + (lane >> 2);
            int g  = nBase + wn * 32 + an * 8 + (lane & 3) * 2;
            #pragma unroll
            for (int half = 0; half < 2; half++) {
                int m = m0 + half * 8;
                float v0 = acc[am][an][half * 2];
                float v1 = acc[am][an][half * 2 + 1];
                if (EP == 0) {                          // relu -> h hi/lo
                    v0 = fmaxf(v0 + biasP[g], 0.f);
                    v1 = fmaxf(v1 + biasP[g + 1], 0.f);
                    store_hilo(oHi, oLo, (size_t)m * HIDDEN + g, v0, v1);
                } else if (EP == 1) {                   // xsub fp32
                    v0 += biasP[g]; v1 += biasP[g + 1];
                    *(float2*)(o32 + (size_t)m * HIDDEN + g) = make_float2(v0, v1);
                } else if (EP == 2) {                   // qkv fp32 split
                    int which = g >> 9, lc = g & 511;
                    const float* bb = (which == 0) ? bq : (which == 1) ? bk : bv;
                    float* dst = (which == 0) ? oq : (which == 1) ? okk : ov;
                    v0 += bb[lc]; v1 += bb[lc + 1];
                    *(float2*)(dst + (size_t)m * HIDDEN + lc) = make_float2(v0, v1);
                } else if (EP == 3) {                   // t hi/lo
                    v0 += biasP[g]; v1 += biasP[g + 1];
                    store_hilo(oHi, oLo, (size_t)m * HIDDEN + g, v0, v1);
                } else if (EP == 4) {                   // out = . + bp + xsub, (b,s) order
                    v0 += biasP[g] + resid[(size_t)m * HIDDEN + g];
                    v1 += biasP[g + 1] + resid[(size_t)m * HIDDEN + g + 1];
                    int bb2 = m & (BATCH - 1), ss = m >> 8;
                    *(float2*)(o32 + ((size_t)((bb2 << 3) + ss)) * HIDDEN + g) = make_float2(v0, v1);
                } else {                                // EP 5: raw split-K partial
                    *(float2*)(oPart + (size_t)m * HIDDEN + g) = make_float2(v0, v1);
                }
            }
        }
    }
}

// ---------------- split-K reduce for GEMM1: h = relu(p0 + p1 + b1) -> hi/lo ----------------
__global__ __launch_bounds__(256) void reduce1_kernel(const float* __restrict__ b1) {
    int i = blockIdx.x * blockDim.x + threadIdx.x;   // float2 index
    if (i >= ROWS * HIDDEN / 2) return;
    const float2* p0 = (const float2*)g_part;
    const float2* p1 = (const float2*)(g_part + ROWS * HIDDEN);
    float2 a = p0[i], b = p1[i];
    int col2 = i & (HIDDEN / 2 - 1);
    int row  = i >> 8;                                // / (HIDDEN/2)
    int s    = row >> 8;
    float v0 = fmaxf(a.x + b.x + b1[s * HIDDEN + col2 * 2],     0.f);
    float v1 = fmaxf(a.y + b.y + b1[s * HIDDEN + col2 * 2 + 1], 0.f);
    store_hilo(g_h_hi, g_h_lo, (size_t)row * HIDDEN + col2 * 2, v0, v1);
}

// ---------------- LayerNorm: xsub fp32 -> xn hi/lo ----------------
__global__ __launch_bounds__(256) void ln_kernel(const float* __restrict__ lng,
                                                 const float* __restrict__ lnb)
{
    int r = blockIdx.x, t = threadIdx.x;
    const float* xs = g_xsub + (size_t)r * HIDDEN;
    float v0 = xs[t], v1 = xs[t + 256];
    float s = v0 + v1, q = v0 * v0 + v1 * v1;
    #pragma unroll
    for (int o = 16; o > 0; o >>= 1) {
        s += __shfl_xor_sync(0xFFFFFFFFu, s, o);
        q += __shfl_xor_sync(0xFFFFFFFFu, q, o);
    }
    __shared__ float ss[8], sq[8];
    int w = t >> 5, l = t & 31;
    if (l == 0) { ss[w] = s; sq[w] = q; }
    __syncthreads();
    if (w == 0) {
        float a = (l < 8) ? ss[l] : 0.f;
        float c = (l < 8) ? sq[l] : 0.f;
        #pragma unroll
        for (int o = 4; o > 0; o >>= 1) {
            a += __shfl_xor_sync(0xFFFFFFFFu, a, o);
            c += __shfl_xor_sync(0xFFFFFFFFu, c, o);
        }
        if (l == 0) { ss[0] = a; sq[0] = c; }
    }
    __syncthreads();
    float mean = ss[0] * (1.f / HIDDEN);
    float var  = sq[0] * (1.f / HIDDEN) - mean * mean;
    float inv  = rsqrtf(var + LN_EPS);
    float o0 = (v0 - mean) * inv * lng[t] + lnb[t];
    float o1 = (v1 - mean) * inv * lng[t + 256] + lnb[t + 256];
    size_t base = (size_t)r * HIDDEN;
    __nv_bfloat16 h0 = __float2bfloat16(o0);
    __nv_bfloat16 h1 = __float2bfloat16(o1);
    g_xn_hi[base + t] = h0;
    g_xn_lo[base + t] = __float2bfloat16(o0 - __bfloat162float(h0));
    g_xn_hi[base + t + 256] = h1;
    g_xn_lo[base + t + 256] = __float2bfloat16(o1 - __bfloat162float(h1));
}

// ---------------- attention: q,k,v fp32 -> ctx hi/lo ----------------
__global__ __launch_bounds__(256) void attn_kernel()
{
    __shared__ float q_s[NUM_SUBNETS][520];
    __shared__ float k_s[NUM_SUBNETS][520];
    __shared__ float sc[HEADS][NUM_SUBNETS][NUM_SUBNETS];

    int b = blockIdx.x;
    int tid = threadIdx.x;

    for (int i = tid; i < NUM_SUBNETS * HIDDEN; i += 256) {
        int m = i >> 9, c = i & 511;
        size_t gi = ((size_t)(m * BATCH + b)) * HIDDEN + c;
        q_s[m][c] = g_q[gi];
        k_s[m][c] = g_k[gi];
    }
    __syncthreads();

    int h = tid >> 5, l = tid & 31;

    #pragma unroll
    for (int pp = 0; pp < 2; pp++) {
        int p = l + pp * 32;
        int m = p >> 3, n = p & 7;
        const float* qp = &q_s[m][h * HEAD_DIM];
        const float* kp = &k_s[n][h * HEAD_DIM];
        float sv = 0.f;
        #pragma unroll
        for (int d = 0; d < HEAD_DIM; d++) sv += qp[d] * kp[d];
        sv *= 0.125f;
        sc[h][m][n] = (m == n) ? 0.f : sv;
    }
    __syncwarp();

    if (l < NUM_SUBNETS) {
        float mx = -1e30f;
        #pragma unroll
        for (int n = 0; n < 8; n++) mx = fmaxf(mx, sc[h][l][n]);
        float e[8], sum = 0.f;
        #pragma unroll
        for (int n = 0; n < 8; n++) { e[n] = expf(sc[h][l][n] - mx); sum += e[n]; }
        float inv = 1.f / sum;
        #pragma unroll
        for (int n = 0; n < 8; n++) sc[h][l][n] = e[n] * inv;
    }
    __syncwarp();

    #pragma unroll
    for (int dd = 0; dd < 2; dd++) {
        int d = l + dd * 32;
        float vv[8];
        #pragma unroll
        for (int n = 0; n < 8; n++)
            vv[n] = g_v[((size_t)(n * BATCH + b)) * HIDDEN + h * HEAD_DIM + d];
        #pragma unroll
        for (int m = 0; m < 8; m++) {
            float cv = 0.f;
            #pragma unroll
            for (int n = 0; n < 8; n++) cv += sc[h][m][n] * vv[n];
            size_t off = ((size_t)(m * BATCH + b)) * HIDDEN + h * HEAD_DIM + d;
            __nv_bfloat16 hi = __float2bfloat16(cv);
            g_ctx_hi[off] = hi;
            g_ctx_lo[off] = __float2bfloat16(cv - __bfloat162float(hi));
        }
    }
}

// ---------------- launch ----------------
extern "C" void kernel_launch(void* const* d_in, const int* in_sizes, int n_in,
                              void* d_out, int out_size)
{
    (void)in_sizes; (void)n_in; (void)out_size;
    const float* x    = (const float*)d_in[0];
    const float* W1   = (const float*)d_in[2];
    const float* b1   = (const float*)d_in[3];
    const float* W2   = (const float*)d_in[4];
    const float* b2   = (const float*)d_in[5];
    const float* ln_g = (const float*)d_in[6];
    const float* ln_b = (const float*)d_in[7];
    const float* Wq   = (const float*)d_in[8];
    const float* bq   = (const float*)d_in[9];
    const float* Wk   = (const float*)d_in[10];
    const float* bk   = (const float*)d_in[11];
    const float* Wv   = (const float*)d_in[12];
    const float* bv   = (const float*)d_in[13];
    const float* Wo   = (const float*)d_in[14];
    const float* bo   = (const float*)d_in[15];
    const float* Wp   = (const float*)d_in[16];
    const float* bp   = (const float*)d_in[17];
    float* out = (float*)d_out;

    __nv_bfloat16 *flat_hi, *flat_lo, *W1T_hi, *W1T_lo, *W2T_hi, *W2T_lo;
    __nv_bfloat16 *WqkvT_hi, *WqkvT_lo, *WoT_hi, *WoT_lo, *WpT_hi, *WpT_lo;
    __nv_bfloat16 *h_hi, *h_lo, *xn_hi, *xn_lo, *ctx_hi, *ctx_lo, *t_hi, *t_lo;
    float *xsub, *pq, *pk, *pv, *part;
    cudaGetSymbolAddress((void**)&flat_hi, g_flat_hi);
    cudaGetSymbolAddress((void**)&flat_lo, g_flat_lo);
    cudaGetSymbolAddress((void**)&W1T_hi,  g_W1T_hi);
    cudaGetSymbolAddress((void**)&W1T_lo,  g_W1T_lo);
    cudaGetSymbolAddress((void**)&W2T_hi,  g_W2T_hi);
    cudaGetSymbolAddress((void**)&W2T_lo,  g_W2T_lo);
    cudaGetSymbolAddress((void**)&WqkvT_hi, g_WqkvT_hi);
    cudaGetSymbolAddress((void**)&WqkvT_lo, g_WqkvT_lo);
    cudaGetSymbolAddress((void**)&WoT_hi,  g_WoT_hi);
    cudaGetSymbolAddress((void**)&WoT_lo,  g_WoT_lo);
    cudaGetSymbolAddress((void**)&WpT_hi,  g_WpT_hi);
    cudaGetSymbolAddress((void**)&WpT_lo,  g_WpT_lo);
    cudaGetSymbolAddress((void**)&h_hi,    g_h_hi);
    cudaGetSymbolAddress((void**)&h_lo,    g_h_lo);
    cudaGetSymbolAddress((void**)&xn_hi,   g_xn_hi);
    cudaGetSymbolAddress((void**)&xn_lo,   g_xn_lo);
    cudaGetSymbolAddress((void**)&ctx_hi,  g_ctx_hi);
    cudaGetSymbolAddress((void**)&ctx_lo,  g_ctx_lo);
    cudaGetSymbolAddress((void**)&t_hi,    g_t_hi);
    cudaGetSymbolAddress((void**)&t_lo,    g_t_lo);
    cudaGetSymbolAddress((void**)&xsub,    g_xsub);
    cudaGetSymbolAddress((void**)&pq,      g_q);
    cudaGetSymbolAddress((void**)&pk,      g_k);
    cudaGetSymbolAddress((void**)&pv,      g_v);
    cudaGetSymbolAddress((void**)&part,    g_part);

    cudaFuncSetAttribute(tc_gemm<1>, cudaFuncAttributeMaxDynamicSharedMemorySize, GEMM_SMEM);
    cudaFuncSetAttribute(tc_gemm<2>, cudaFuncAttributeMaxDynamicSharedMemorySize, GEMM_SMEM);
    cudaFuncSetAttribute(tc_gemm<3>, cudaFuncAttributeMaxDynamicSharedMemorySize, GEMM_SMEM);
    cudaFuncSetAttribute(tc_gemm<4>, cudaFuncAttributeMaxDynamicSharedMemorySize, GEMM_SMEM);
    cudaFuncSetAttribute(tc_gemm<5>, cudaFuncAttributeMaxDynamicSharedMemorySize, GEMM_SMEM);

    // ---- input conversions ----
    extract_kernel<<<(ROWS * KPAD1 / 4 + 255) / 256, 256>>>(x);
    wconv_w1_kernel<<<dim3(KPAD1 / 32, HIDDEN / 32, NUM_SUBNETS), 256>>>(W1);

    W13 wa;
    for (int z = 0; z < 8; z++) {
        wa.src[z] = W2 + (size_t)z * HIDDEN * HIDDEN;
        wa.dhi[z] = W2T_hi + (size_t)z * HIDDEN * HIDDEN;
        wa.dlo[z] = W2T_lo + (size_t)z * HIDDEN * HIDDEN;
    }
    const float* srcs[5] = { Wq, Wk, Wv, Wo, Wp };
    __nv_bfloat16* dhis[5] = { WqkvT_hi, WqkvT_hi + 512 * 512, WqkvT_hi + 1024 * 512, WoT_hi, WpT_hi };
    __nv_bfloat16* dlos[5] = { WqkvT_lo, WqkvT_lo + 512 * 512, WqkvT_lo + 1024 * 512, WoT_lo, WpT_lo };
    for (int z = 0; z < 5; z++) {
        wa.src[8 + z] = srcs[z];
        wa.dhi[8 + z] = dhis[z];
        wa.dlo[8 + z] = dlos[z];
    }
    wconv512_kernel<<<dim3(16, 16, 13), 256>>>(wa);

    dim3 g1(HIDDEN / BN, ROWS / BM, 2);       // 8 x 32 x 2 = 512 CTAs (split-K)
    dim3 g512(HIDDEN / BN, ROWS / BM);        // 8 x 32 = 256 CTAs
    dim3 gqkv(3 * HIDDEN / BN, ROWS / BM);    // 24 x 32 = 768 CTAs

    // GEMM1 (split-K x2): partials, then reduce -> h = relu(. + b1)
    tc_gemm<5><<<g1, 256, GEMM_SMEM>>>(flat_hi, flat_lo, KPAD1, W1T_hi, W1T_lo, KPAD1,
        (long)HIDDEN * KPAD1, (KPAD1 / BK) / 2, nullptr, part, nullptr, nullptr,
        nullptr, nullptr, nullptr, nullptr, nullptr, nullptr, nullptr);
    reduce1_kernel<<<(ROWS * HIDDEN / 2 + 255) / 256, 256>>>(b1);
    // GEMM2: xsub = h @ W2 + b2
    tc_gemm<1><<<g512, 256, GEMM_SMEM>>>(h_hi, h_lo, HIDDEN, W2T_hi, W2T_lo, HIDDEN,
        (long)HIDDEN * HIDDEN, HIDDEN / BK, b2, xsub, nullptr, nullptr,
        nullptr, nullptr, nullptr, nullptr, nullptr, nullptr, nullptr);
    // LN -> xn hi/lo
    ln_kernel<<<ROWS, 256>>>(ln_g, ln_b);
    // QKV fused
    tc_gemm<2><<<gqkv, 256, GEMM_SMEM>>>(xn_hi, xn_lo, HIDDEN, WqkvT_hi, WqkvT_lo, HIDDEN,
        0L, HIDDEN / BK, nullptr, nullptr, nullptr, nullptr,
        nullptr, pq, pk, pv, bq, bk, bv);
    // attention -> ctx hi/lo
    attn_kernel<<<BATCH, 256>>>();
    // O: t = ctx @ Wo + bo
    tc_gemm<3><<<g512, 256, GEMM_SMEM>>>(ctx_hi, ctx_lo, HIDDEN, WoT_hi, WoT_lo, HIDDEN,
        0L, HIDDEN / BK, bo, nullptr, t_hi, t_lo,
        nullptr, nullptr, nullptr, nullptr, nullptr, nullptr, nullptr);
    // P: out = t @ Wp + bp + xsub (permuted to (b,s))
    tc_gemm<4><<<g512, 256, GEMM_SMEM>>>(t_hi, t_lo, HIDDEN, WpT_hi, WpT_lo, HIDDEN,
        0L, HIDDEN / BK, bp, out, nullptr, nullptr,
        xsub, nullptr, nullptr, nullptr, nullptr, nullptr, nullptr);
}

// round 8
// speedup vs baseline: 1.2846x; 1.2846x over previous
#include <cuda_runtime.h>
#include <cuda_fp16.h>
#include <math.h>
#include <cstdint>

// ---------------- problem constants ----------------
#define NUM_SUBNETS 8
#define REGIONS     50
#define TOTAL_R     400
#define HIDDEN      512
#define HEADS       8
#define HEAD_DIM    64
#define BATCH       256
#define FLAT        2500
#define ROWS        (NUM_SUBNETS * BATCH)   // 2048
#define LN_EPS      1e-5f
#define KPAD1       2560                    // FLAT padded to multiple of 64

// GEMM tiling: A single fp16, W split hi/lo fp16. C = A*Wh + A*Wl.
#define BM 64
#define BN 64
#define BK 64
#define ASTRIDE 144                         // bytes per 64-col fp16 row (128 + 16 pad)
#define T_BYTES (BM * ASTRIDE)              // 9216 per tile array
#define STAGE   (3 * T_BYTES)               // 27648 (A, Bhi, Blo)
#define NSTAGE  4
#define GEMM_SMEM (NSTAGE * STAGE)          // 110592 -> 2 CTAs/SM

typedef unsigned long long u64;

// ---------------- scratch (device globals) ----------------
__device__ __half g_flat[ROWS * KPAD1];
__device__ __half g_W1T_hi[NUM_SUBNETS * HIDDEN * KPAD1];
__device__ __half g_W1T_lo[NUM_SUBNETS * HIDDEN * KPAD1];
__device__ __half g_W2T_hi[NUM_SUBNETS * HIDDEN * HIDDEN];
__device__ __half g_W2T_lo[NUM_SUBNETS * HIDDEN * HIDDEN];
__device__ __half g_WqkvT_hi[3 * HIDDEN * HIDDEN];
__device__ __half g_WqkvT_lo[3 * HIDDEN * HIDDEN];
__device__ __half g_WoT_hi[HIDDEN * HIDDEN];
__device__ __half g_WoT_lo[HIDDEN * HIDDEN];
__device__ __half g_WpT_hi[HIDDEN * HIDDEN];
__device__ __half g_WpT_lo[HIDDEN * HIDDEN];

__device__ __half g_h  [ROWS * HIDDEN];
__device__ float  g_xsub[ROWS * HIDDEN];
__device__ __half g_xn [ROWS * HIDDEN];
__device__ float  g_q  [ROWS * HIDDEN];
__device__ float  g_k  [ROWS * HIDDEN];
__device__ float  g_v  [ROWS * HIDDEN];
__device__ __half g_ctx[ROWS * HIDDEN];
__device__ __half g_t  [ROWS * HIDDEN];

// ---------------- PTX helpers (sm_80-ratified only) ----------------
__device__ __forceinline__ uint32_t smem_u32(const void* p) {
    uint32_t a;
    asm("{ .reg .u64 t; cvta.to.shared.u64 t, %1; cvt.u32.u64 %0, t; }" : "=r"(a) : "l"(p));
    return a;
}
__device__ __forceinline__ void cpa16(uint32_t s, const void* g) {
    asm volatile("cp.async.cg.shared.global [%0], [%1], 16;" :: "r"(s), "l"(g));
}
__device__ __forceinline__ void cpa_commit() {
    asm volatile("cp.async.commit_group;" ::: "memory");
}
template<int N> __device__ __forceinline__ void cpa_wait() {
    asm volatile("cp.async.wait_group %0;" :: "n"(N) : "memory");
}
__device__ __forceinline__ void ldm4(uint32_t a, uint32_t* r) {
    asm volatile("ldmatrix.sync.aligned.m8n8.x4.shared.b16 {%0,%1,%2,%3}, [%4];"
        : "=r"(r[0]), "=r"(r[1]), "=r"(r[2]), "=r"(r[3]) : "r"(a));
}
__device__ __forceinline__ void mma16816(float* c, const uint32_t* a, uint32_t b0, uint32_t b1) {
    asm volatile("mma.sync.aligned.m16n8k16.row.col.f32.f16.f16.f32 "
        "{%0,%1,%2,%3},{%4,%5,%6,%7},{%8,%9},{%0,%1,%2,%3};"
        : "+f"(c[0]), "+f"(c[1]), "+f"(c[2]), "+f"(c[3])
        : "r"(a[0]), "r"(a[1]), "r"(a[2]), "r"(a[3]), "r"(b0), "r"(b1));
}

__device__ __forceinline__ void store_h2(__half* dst, size_t off, float v0, float v1) {
    *(__half2*)(dst + off) = __floats2half2_rn(v0, v1);
}

union H4 { uint2 u; __half2 p[2]; };

// split weights: hi = rn(v), lo = rn(v - hi)
__device__ __forceinline__ void wsplit4(const float* v, H4& hv, H4& lv) {
    __half h0 = __float2half_rn(v[0]);
    __half h1 = __float2half_rn(v[1]);
    __half h2 = __float2half_rn(v[2]);
    __half h3 = __float2half_rn(v[3]);
    hv.p[0] = __halves2half2(h0, h1);
    hv.p[1] = __halves2half2(h2, h3);
    lv.p[0] = __halves2half2(__float2half_rn(v[0] - __half2float(h0)),
                             __float2half_rn(v[1] - __half2float(h1)));
    lv.p[1] = __halves2half2(__float2half_rn(v[2] - __half2float(h2)),
                             __float2half_rn(v[3] - __half2float(h3)));
}

// ---------------- kernel: extract diagonal blocks -> fp16 (4 elems/thread) ----------------
__global__ void extract_kernel(const float* __restrict__ x) {
    int q = blockIdx.x * blockDim.x + threadIdx.x;        // quad index
    if (q >= ROWS * KPAD1 / 4) return;
    int f0 = (q % (KPAD1 / 4)) * 4;
    int sb = q / (KPAD1 / 4);
    int b  = sb & (BATCH - 1);
    int s  = sb >> 8;
    const float* xb = x + (size_t)b * (TOTAL_R * TOTAL_R);
    float v[4];
    #pragma unroll
    for (int e = 0; e < 4; e++) {
        int f = f0 + e;
        float vv = 0.f;
        if (f < FLAT) {
            int i = f / REGIONS;
            int j = f - i * REGIONS;
            vv = xb[(s * REGIONS + i) * TOTAL_R + (s * REGIONS + j)];
        }
        v[e] = vv;
    }
    H4 hv;
    hv.p[0] = __floats2half2_rn(v[0], v[1]);
    hv.p[1] = __floats2half2_rn(v[2], v[3]);
    *(uint2*)(g_flat + (size_t)sb * KPAD1 + f0) = hv.u;
}

// ---------------- W1 transpose+split: [s][2500][512] -> [s][512][2560] fp16 hi/lo ----------------
__global__ void wconv_w1_kernel(const float* __restrict__ src) {
    __shared__ float tile[32][33];
    int k0 = blockIdx.x * 32, n0 = blockIdx.y * 32, z = blockIdx.z;
    const float* sp = src + (size_t)z * FLAT * HIDDEN;
    size_t dbase = (size_t)z * HIDDEN * KPAD1;
    int tid = threadIdx.x;
    int tx = tid & 31, ty = tid >> 5;       // 256 threads
    #pragma unroll
    for (int r = 0; r < 4; r++) {
        int k = k0 + ty + r * 8;
        tile[ty + r * 8][tx] = (k < FLAT) ? sp[(size_t)k * HIDDEN + n0 + tx] : 0.f;
    }
    __syncthreads();
    int n = tid >> 3, kq = (tid & 7) * 4;
    float v[4];
    #pragma unroll
    for (int i = 0; i < 4; i++) v[i] = tile[kq + i][n];
    H4 hv, lv; wsplit4(v, hv, lv);
    size_t off = dbase + (size_t)(n0 + n) * KPAD1 + k0 + kq;
    *(uint2*)(g_W1T_hi + off) = hv.u;
    *(uint2*)(g_W1T_lo + off) = lv.u;
}

// ---------------- batched 512x512 transpose+split (13 slices, one launch) ----------------
struct W13 {
    const float* src[13];
    __half* dhi[13];
    __half* dlo[13];
};
__global__ void wconv512_kernel(W13 a) {
    __shared__ float tile[32][33];
    int z = blockIdx.z;
    const float* sp = a.src[z];
    __half* dhi = a.dhi[z];
    __half* dlo = a.dlo[z];
    int k0 = blockIdx.x * 32, n0 = blockIdx.y * 32;
    int tid = threadIdx.x;
    int tx = tid & 31, ty = tid >> 5;
    #pragma unroll
    for (int r = 0; r < 4; r++) {
        int k = k0 + ty + r * 8;
        tile[ty + r * 8][tx] = sp[(size_t)k * HIDDEN + n0 + tx];
    }
    __syncthreads();
    int n = tid >> 3, kq = (tid & 7) * 4;
    float v[4];
    #pragma unroll
    for (int i = 0; i < 4; i++) v[i] = tile[kq + i][n];
    H4 hv, lv; wsplit4(v, hv, lv);
    size_t off = (size_t)(n0 + n) * HIDDEN + k0 + kq;
    *(uint2*)(dhi + off) = hv.u;
    *(uint2*)(dlo + off) = lv.u;
}

// ---------------- mma.sync GEMM: C[2048][N] = A[2048][K] * W^T + epilogue ----------------
// C = A*Wh + A*Wl, fp32 accum. BM=BN=64, BK=64, 4-stage cp.async pipeline.
// 8 warps as (wm 2) x (wn 2) x (wk 2): warp tile 32x32, K split across wk,
// reduced through SMEM. MMAs term-major (acc RAW distance 8). 2 CTAs/SM.
// EP: 0 relu->fp16 | 1 f32 | 2 qkv split f32 | 3 fp16 | 4 resid+permute f32
template<int EP>
__global__ __launch_bounds__(256, 2) void tc_gemm(
    const __half* __restrict__ A, int sA,
    const __half* __restrict__ Bhi, const __half* __restrict__ Blo, int sB,
    long bSub, int Ksteps,
    const float* __restrict__ bias,
    float* __restrict__ o32,
    __half* __restrict__ oH,
    const float* __restrict__ resid,
    float* __restrict__ oq, float* __restrict__ okk, float* __restrict__ ov,
    const float* __restrict__ bq, const float* __restrict__ bk, const float* __restrict__ bv)
{
    extern __shared__ __align__(128) char smem[];
    const uint32_t sbase = smem_u32(smem);
    const int tid = threadIdx.x;
    const int mBase = blockIdx.y * BM;
    const int nBase = blockIdx.x * BN;
    const int sIdx = blockIdx.y >> 2;        // 4 M-tiles (256 rows) per subnet

    const __half* aP = A + (size_t)mBase * sA;
    size_t boff = (bSub > 0 ? (size_t)sIdx * (size_t)bSub : 0) + (size_t)nBase * sB;
    const __half* bH = Bhi + boff;
    const __half* bL = Blo + boff;
    const float* biasP = bias ? (bias + (bSub > 0 ? sIdx * HIDDEN : 0)) : bias;

    // ---- async-copy one K-chunk; ALWAYS commits exactly one group ----
    auto issue = [&](int chunk) {
        if (chunk < Ksteps) {
            const uint32_t st = sbase + (chunk % NSTAGE) * STAGE;
            const int k0 = chunk * BK;
            // A: 64 rows x 8 16B-chunks = 512 -> 2/thread
            #pragma unroll
            for (int i = 0; i < 2; i++) {
                int idx = tid + i * 256;
                int row = idx >> 3, c = idx & 7;
                cpa16(st + row * ASTRIDE + c * 16, aP + (size_t)row * sA + k0 + c * 8);
            }
            // B hi+lo: 2 x 512 -> 4/thread
            #pragma unroll
            for (int i = 0; i < 2; i++) {
                int idx = tid + i * 256;
                int row = idx >> 3, c = idx & 7;
                uint32_t so = st + T_BYTES + row * ASTRIDE + c * 16;
                cpa16(so,           bH + (size_t)row * sB + k0 + c * 8);
                cpa16(so + T_BYTES, bL + (size_t)row * sB + k0 + c * 8);
            }
        }
        cpa_commit();
    };

    issue(0); issue(1); issue(2);

    const int wid = tid >> 5, lane = tid & 31;
    const int wk = wid >> 2;                 // 0/1 : handles kk = 2*wk + {0,1}
    const int wm = (wid >> 1) & 1;           // 32-row half
    const int wn = wid & 1;                  // 32-col half
    const uint32_t lrow = lane & 15;
    const uint32_t lcol = (lane >> 4) * 16;

    float acc[2][4][4];                      // [m16 tile][n8 tile][frag]
    #pragma unroll
    for (int i = 0; i < 2; i++)
        #pragma unroll
        for (int j = 0; j < 4; j++)
            #pragma unroll
            for (int t = 0; t < 4; t++) acc[i][j][t] = 0.f;

    for (int s = 0; s < Ksteps; ++s) {
        cpa_wait<2>();                 // stage s landed (3 in flight)
        __syncthreads();               // all warps done with buffer (s-1)%4
        issue(s + 3);                  // refill freed buffer, overlaps compute
        const uint32_t st = sbase + (s % NSTAGE) * STAGE;
        #pragma unroll
        for (int j = 0; j < 2; ++j) {
            const int kk = wk * 2 + j;
            uint32_t aF[2][4], bHf[2][4], bLf[2][4];
            #pragma unroll
            for (int am = 0; am < 2; am++) {
                uint32_t ad = st + (wm * 32 + am * 16 + lrow) * ASTRIDE + kk * 32 + lcol;
                ldm4(ad, aF[am]);
            }
            #pragma unroll
            for (int bt = 0; bt < 2; bt++) {
                uint32_t bd = st + T_BYTES + (wn * 32 + bt * 16 + lrow) * ASTRIDE + kk * 32 + lcol;
                ldm4(bd,           bHf[bt]);
                ldm4(bd + T_BYTES, bLf[bt]);
            }
            // term-major: acc reuse distance 8
            #pragma unroll
            for (int am = 0; am < 2; am++)
                #pragma unroll
                for (int bt = 0; bt < 2; bt++) {
                    mma16816(acc[am][2*bt],   aF[am], bHf[bt][0], bHf[bt][2]);
                    mma16816(acc[am][2*bt+1], aF[am], bHf[bt][1], bHf[bt][3]);
                }
            #pragma unroll
            for (int am = 0; am < 2; am++)
                #pragma unroll
                for (int bt = 0; bt < 2; bt++) {
                    mma16816(acc[am][2*bt],   aF[am], bLf[bt][0], bLf[bt][2]);
                    mma16816(acc[am][2*bt+1], aF[am], bLf[bt][1], bLf[bt][3]);
                }
        }
    }

    // ---- reduce wk=1 partial sums into wk=0 via SMEM (stages are dead now) ----
    __syncthreads();
    float* red = (float*)smem;               // 4 regions of [32][34] floats
    float* rbase = red + (wm * 2 + wn) * (32 * 34);
    if (wk == 1) {
        #pragma unroll
        for (int am = 0; am < 2; am++)
            #pragma unroll
            for (int an = 0; an < 4; an++)
                #pragma unroll
                for (int t = 0; t < 4; t++) {
                    int row = am * 16 + (lane >> 2) + (t >> 1) * 8;
                    int col = an * 8 + (lane & 3) * 2 + (t & 1);
                    rbase[row * 34 + col] = acc[am][an][t];
                }
    }
    __syncthreads();
    if (wk == 1) return;
    #pragma unroll
    for (int am = 0; am < 2; am++)
        #pragma unroll
        for (int an = 0; an < 4; an++)
            #pragma unroll
            for (int t = 0; t < 4; t++) {
                int row = am * 16 + (lane >> 2) + (t >> 1) * 8;
                int col = an * 8 + (lane & 3) * 2 + (t & 1);
                acc[am][an][t] += rbase[row * 34 + col];
            }

    // ---- epilogue (wk=0 warps only): registers -> global ----
    #pragma unroll
    for (int am = 0; am < 2; am++) {
        #pragma unroll
        for (int an = 0; an < 4; an++) {
            int m0 = mBase + wm * 32 + am * 16 + (lane >> 2);
            int g  = nBase + wn * 32 + an * 8 + (lane & 3) * 2;
            #pragma unroll
            for (int half = 0; half < 2; half++) {
                int m = m0 + half * 8;
                float v0 = acc[am][an][half * 2];
                float v1 = acc[am][an][half * 2 + 1];
                if (EP == 0) {                          // relu -> fp16
                    v0 = fmaxf(v0 + biasP[g], 0.f);
                    v1 = fmaxf(v1 + biasP[g + 1], 0.f);
                    store_h2(oH, (size_t)m * HIDDEN + g, v0, v1);
                } else if (EP == 1) {                   // xsub fp32
                    v0 += biasP[g]; v1 += biasP[g + 1];
                    *(float2*)(o32 + (size_t)m * HIDDEN + g) = make_float2(v0, v1);
                } else if (EP == 2) {                   // qkv fp32 split
                    int which = g >> 9, lc = g & 511;
                    const float* bb = (which == 0) ? bq : (which == 1) ? bk : bv;
                    float* dst = (which == 0) ? oq : (which == 1) ? okk : ov;
                    v0 += bb[lc]; v1 += bb[lc + 1];
                    *(float2*)(dst + (size_t)m * HIDDEN + lc) = make_float2(v0, v1);
                } else if (EP == 3) {                   // fp16 out (t)
                    v0 += biasP[g]; v1 += biasP[g + 1];
                    store_h2(oH, (size_t)m * HIDDEN + g, v0, v1);
                } else {                                // out = . + bp + xsub, (b,s) order
                    v0 += biasP[g] + resid[(size_t)m * HIDDEN + g];
                    v1 += biasP[g + 1] + resid[(size_t)m * HIDDEN + g + 1];
                    int bb2 = m & (BATCH - 1), ss = m >> 8;
                    *(float2*)(o32 + ((size_t)((bb2 << 3) + ss)) * HIDDEN + g) = make_float2(v0, v1);
                }
            }
        }
    }
}

// ---------------- LayerNorm: xsub fp32 -> xn fp16 ----------------
__global__ __launch_bounds__(256) void ln_kernel(const float* __restrict__ lng,
                                                 const float* __restrict__ lnb)
{
    int r = blockIdx.x, t = threadIdx.x;
    const float* xs = g_xsub + (size_t)r * HIDDEN;
    float v0 = xs[t], v1 = xs[t + 256];
    float s = v0 + v1, q = v0 * v0 + v1 * v1;
    #pragma unroll
    for (int o = 16; o > 0; o >>= 1) {
        s += __shfl_xor_sync(0xFFFFFFFFu, s, o);
        q += __shfl_xor_sync(0xFFFFFFFFu, q, o);
    }
    __shared__ float ss[8], sq[8];
    int w = t >> 5, l = t & 31;
    if (l == 0) { ss[w] = s; sq[w] = q; }
    __syncthreads();
    if (w == 0) {
        float a = (l < 8) ? ss[l] : 0.f;
        float c = (l < 8) ? sq[l] : 0.f;
        #pragma unroll
        for (int o = 4; o > 0; o >>= 1) {
            a += __shfl_xor_sync(0xFFFFFFFFu, a, o);
            c += __shfl_xor_sync(0xFFFFFFFFu, c, o);
        }
        if (l == 0) { ss[0] = a; sq[0] = c; }
    }
    __syncthreads();
    float mean = ss[0] * (1.f / HIDDEN);
    float var  = sq[0] * (1.f / HIDDEN) - mean * mean;
    float inv  = rsqrtf(var + LN_EPS);
    float o0 = (v0 - mean) * inv * lng[t] + lnb[t];
    float o1 = (v1 - mean) * inv * lng[t + 256] + lnb[t + 256];
    size_t base = (size_t)r * HIDDEN;
    g_xn[base + t]       = __float2half_rn(o0);
    g_xn[base + t + 256] = __float2half_rn(o1);
}

// ---------------- attention: q,k,v fp32 -> ctx fp16 ----------------
__global__ __launch_bounds__(256) void attn_kernel()
{
    __shared__ float q_s[NUM_SUBNETS][520];
    __shared__ float k_s[NUM_SUBNETS][520];
    __shared__ float sc[HEADS][NUM_SUBNETS][NUM_SUBNETS];

    int b = blockIdx.x;
    int tid = threadIdx.x;

    for (int i = tid; i < NUM_SUBNETS * HIDDEN; i += 256) {
        int m = i >> 9, c = i & 511;
        size_t gi = ((size_t)(m * BATCH + b)) * HIDDEN + c;
        q_s[m][c] = g_q[gi];
        k_s[m][c] = g_k[gi];
    }
    __syncthreads();

    int h = tid >> 5, l = tid & 31;

    #pragma unroll
    for (int pp = 0; pp < 2; pp++) {
        int p = l + pp * 32;
        int m = p >> 3, n = p & 7;
        const float* qp = &q_s[m][h * HEAD_DIM];
        const float* kp = &k_s[n][h * HEAD_DIM];
        float sv = 0.f;
        #pragma unroll
        for (int d = 0; d < HEAD_DIM; d++) sv += qp[d] * kp[d];
        sv *= 0.125f;
        sc[h][m][n] = (m == n) ? 0.f : sv;
    }
    __syncwarp();

    if (l < NUM_SUBNETS) {
        float mx = -1e30f;
        #pragma unroll
        for (int n = 0; n < 8; n++) mx = fmaxf(mx, sc[h][l][n]);
        float e[8], sum = 0.f;
        #pragma unroll
        for (int n = 0; n < 8; n++) { e[n] = expf(sc[h][l][n] - mx); sum += e[n]; }
        float inv = 1.f / sum;
        #pragma unroll
        for (int n = 0; n < 8; n++) sc[h][l][n] = e[n] * inv;
    }
    __syncwarp();

    #pragma unroll
    for (int dd = 0; dd < 2; dd++) {
        int d = l + dd * 32;
        float vv[8];
        #pragma unroll
        for (int n = 0; n < 8; n++)
            vv[n] = g_v[((size_t)(n * BATCH + b)) * HIDDEN + h * HEAD_DIM + d];
        #pragma unroll
        for (int m = 0; m < 8; m++) {
            float cv = 0.f;
            #pragma unroll
            for (int n = 0; n < 8; n++) cv += sc[h][m][n] * vv[n];
            g_ctx[((size_t)(m * BATCH + b)) * HIDDEN + h * HEAD_DIM + d] = __float2half_rn(cv);
        }
    }
}

// ---------------- launch ----------------
extern "C" void kernel_launch(void* const* d_in, const int* in_sizes, int n_in,
                              void* d_out, int out_size)
{
    (void)in_sizes; (void)n_in; (void)out_size;
    const float* x    = (const float*)d_in[0];
    const float* W1   = (const float*)d_in[2];
    const float* b1   = (const float*)d_in[3];
    const float* W2   = (const float*)d_in[4];
    const float* b2   = (const float*)d_in[5];
    const float* ln_g = (const float*)d_in[6];
    const float* ln_b = (const float*)d_in[7];
    const float* Wq   = (const float*)d_in[8];
    const float* bq   = (const float*)d_in[9];
    const float* Wk   = (const float*)d_in[10];
    const float* bk   = (const float*)d_in[11];
    const float* Wv   = (const float*)d_in[12];
    const float* bv   = (const float*)d_in[13];
    const float* Wo   = (const float*)d_in[14];
    const float* bo   = (const float*)d_in[15];
    const float* Wp   = (const float*)d_in[16];
    const float* bp   = (const float*)d_in[17];
    float* out = (float*)d_out;

    __half *flat, *W1T_hi, *W1T_lo, *W2T_hi, *W2T_lo;
    __half *WqkvT_hi, *WqkvT_lo, *WoT_hi, *WoT_lo, *WpT_hi, *WpT_lo;
    __half *h, *xn, *ctx, *t;
    float *xsub, *pq, *pk, *pv;
    cudaGetSymbolAddress((void**)&flat,    g_flat);
    cudaGetSymbolAddress((void**)&W1T_hi,  g_W1T_hi);
    cudaGetSymbolAddress((void**)&W1T_lo,  g_W1T_lo);
    cudaGetSymbolAddress((void**)&W2T_hi,  g_W2T_hi);
    cudaGetSymbolAddress((void**)&W2T_lo,  g_W2T_lo);
    cudaGetSymbolAddress((void**)&WqkvT_hi, g_WqkvT_hi);
    cudaGetSymbolAddress((void**)&WqkvT_lo, g_WqkvT_lo);
    cudaGetSymbolAddress((void**)&WoT_hi,  g_WoT_hi);
    cudaGetSymbolAddress((void**)&WoT_lo,  g_WoT_lo);
    cudaGetSymbolAddress((void**)&WpT_hi,  g_WpT_hi);
    cudaGetSymbolAddress((void**)&WpT_lo,  g_WpT_lo);
    cudaGetSymbolAddress((void**)&h,       g_h);
    cudaGetSymbolAddress((void**)&xn,      g_xn);
    cudaGetSymbolAddress((void**)&ctx,     g_ctx);
    cudaGetSymbolAddress((void**)&t,       g_t);
    cudaGetSymbolAddress((void**)&xsub,    g_xsub);
    cudaGetSymbolAddress((void**)&pq,      g_q);
    cudaGetSymbolAddress((void**)&pk,      g_k);
    cudaGetSymbolAddress((void**)&pv,      g_v);

    cudaFuncSetAttribute(tc_gemm<0>, cudaFuncAttributeMaxDynamicSharedMemorySize, GEMM_SMEM);
    cudaFuncSetAttribute(tc_gemm<1>, cudaFuncAttributeMaxDynamicSharedMemorySize, GEMM_SMEM);
    cudaFuncSetAttribute(tc_gemm<2>, cudaFuncAttributeMaxDynamicSharedMemorySize, GEMM_SMEM);
    cudaFuncSetAttribute(tc_gemm<3>, cudaFuncAttributeMaxDynamicSharedMemorySize, GEMM_SMEM);
    cudaFuncSetAttribute(tc_gemm<4>, cudaFuncAttributeMaxDynamicSharedMemorySize, GEMM_SMEM);

    // ---- input conversions ----
    extract_kernel<<<(ROWS * KPAD1 / 4 + 255) / 256, 256>>>(x);
    wconv_w1_kernel<<<dim3(KPAD1 / 32, HIDDEN / 32, NUM_SUBNETS), 256>>>(W1);

    W13 wa;
    for (int z = 0; z < 8; z++) {
        wa.src[z] = W2 + (size_t)z * HIDDEN * HIDDEN;
        wa.dhi[z] = W2T_hi + (size_t)z * HIDDEN * HIDDEN;
        wa.dlo[z] = W2T_lo + (size_t)z * HIDDEN * HIDDEN;
    }
    const float* srcs[5] = { Wq, Wk, Wv, Wo, Wp };
    __half* dhis[5] = { WqkvT_hi, WqkvT_hi + 512 * 512, WqkvT_hi + 1024 * 512, WoT_hi, WpT_hi };
    __half* dlos[5] = { WqkvT_lo, WqkvT_lo + 512 * 512, WqkvT_lo + 1024 * 512, WoT_lo, WpT_lo };
    for (int z = 0; z < 5; z++) {
        wa.src[8 + z] = srcs[z];
        wa.dhi[8 + z] = dhis[z];
        wa.dlo[8 + z] = dlos[z];
    }
    wconv512_kernel<<<dim3(16, 16, 13), 256>>>(wa);

    dim3 g512(HIDDEN / BN, ROWS / BM);        // 8 x 32 = 256 CTAs
    dim3 gqkv(3 * HIDDEN / BN, ROWS / BM);    // 24 x 32 = 768 CTAs

    // GEMM1: h = relu(flat @ W1 + b1) -> fp16
    tc_gemm<0><<<g512, 256, GEMM_SMEM>>>(flat, KPAD1, W1T_hi, W1T_lo, KPAD1,
        (long)HIDDEN * KPAD1, KPAD1 / BK, b1, nullptr, h,
        nullptr, nullptr, nullptr, nullptr, nullptr, nullptr, nullptr);
    // GEMM2: xsub = h @ W2 + b2 (fp32)
    tc_gemm<1><<<g512, 256, GEMM_SMEM>>>(h, HIDDEN, W2T_hi, W2T_lo, HIDDEN,
        (long)HIDDEN * HIDDEN, HIDDEN / BK, b2, xsub, nullptr,
        nullptr, nullptr, nullptr, nullptr, nullptr, nullptr, nullptr);
    // LN -> xn fp16
    ln_kernel<<<ROWS, 256>>>(ln_g, ln_b);
    // QKV fused (fp32 outputs)
    tc_gemm<2><<<gqkv, 256, GEMM_SMEM>>>(xn, HIDDEN, WqkvT_hi, WqkvT_lo, HIDDEN,
        0L, HIDDEN / BK, nullptr, nullptr, nullptr,
        nullptr, pq, pk, pv, bq, bk, bv);
    // attention -> ctx fp16
    attn_kernel<<<BATCH, 256>>>();
    // O: t = ctx @ Wo + bo -> fp16
    tc_gemm<3><<<g512, 256, GEMM_SMEM>>>(ctx, HIDDEN, WoT_hi, WoT_lo, HIDDEN,
        0L, HIDDEN / BK, bo, nullptr, t,
        nullptr, nullptr, nullptr, nullptr, nullptr, nullptr, nullptr);
    // P: out = t @ Wp + bp + xsub (permuted to (b,s))
    tc_gemm<4><<<g512, 256, GEMM_SMEM>>>(t, HIDDEN, WpT_hi, WpT_lo, HIDDEN,
        0L, HIDDEN / BK, bp, out, nullptr,
        xsub, nullptr, nullptr, nullptr, nullptr, nullptr, nullptr);
}

// round 9
// speedup vs baseline: 1.4733x; 1.1470x over previous
#include <cuda_runtime.h>
#include <cuda_fp16.h>
#include <math.h>
#include <cstdint>

// ---------------- problem constants ----------------
#define NUM_SUBNETS 8
#define REGIONS     50
#define TOTAL_R     400
#define HIDDEN      512
#define HEADS       8
#define HEAD_DIM    64
#define BATCH       256
#define FLAT        2500
#define ROWS        (NUM_SUBNETS * BATCH)   // 2048
#define LN_EPS      1e-5f
#define KPAD1       2560                    // FLAT padded to multiple of 64

// GEMM tiling: A single fp16; W either single fp16 (TERMS=1) or split hi/lo (TERMS=2).
#define BM 64
#define BN 64
#define BK 64
#define ASTRIDE 144                         // bytes per 64-col fp16 row (128 + 16 pad)
#define T_BYTES (BM * ASTRIDE)              // 9216 per tile array
#define NSTAGE  4

typedef unsigned long long u64;

// ---------------- scratch (device globals) ----------------
__device__ __half g_flat[ROWS * KPAD1];
__device__ __half g_W1T_hi[NUM_SUBNETS * HIDDEN * KPAD1];
__device__ __half g_W2T_hi[NUM_SUBNETS * HIDDEN * HIDDEN];
__device__ __half g_W2T_lo[NUM_SUBNETS * HIDDEN * HIDDEN];
__device__ __half g_WqkvT_hi[3 * HIDDEN * HIDDEN];
__device__ __half g_WqkvT_lo[3 * HIDDEN * HIDDEN];
__device__ __half g_WoT_hi[HIDDEN * HIDDEN];
__device__ __half g_WoT_lo[HIDDEN * HIDDEN];
__device__ __half g_WpT_hi[HIDDEN * HIDDEN];
__device__ __half g_WpT_lo[HIDDEN * HIDDEN];

__device__ __half g_h  [ROWS * HIDDEN];
__device__ float  g_xsub[ROWS * HIDDEN];
__device__ __half g_xn [ROWS * HIDDEN];
__device__ float  g_q  [ROWS * HIDDEN];
__device__ float  g_k  [ROWS * HIDDEN];
__device__ float  g_v  [ROWS * HIDDEN];
__device__ __half g_ctx[ROWS * HIDDEN];
__device__ __half g_t  [ROWS * HIDDEN];

// ---------------- PTX helpers (sm_80-ratified only) ----------------
__device__ __forceinline__ uint32_t smem_u32(const void* p) {
    uint32_t a;
    asm("{ .reg .u64 t; cvta.to.shared.u64 t, %1; cvt.u32.u64 %0, t; }" : "=r"(a) : "l"(p));
    return a;
}
__device__ __forceinline__ void cpa16(uint32_t s, const void* g) {
    asm volatile("cp.async.cg.shared.global [%0], [%1], 16;" :: "r"(s), "l"(g));
}
__device__ __forceinline__ void cpa_commit() {
    asm volatile("cp.async.commit_group;" ::: "memory");
}
template<int N> __device__ __forceinline__ void cpa_wait() {
    asm volatile("cp.async.wait_group %0;" :: "n"(N) : "memory");
}
__device__ __forceinline__ void ldm4(uint32_t a, uint32_t* r) {
    asm volatile("ldmatrix.sync.aligned.m8n8.x4.shared.b16 {%0,%1,%2,%3}, [%4];"
        : "=r"(r[0]), "=r"(r[1]), "=r"(r[2]), "=r"(r[3]) : "r"(a));
}
__device__ __forceinline__ void mma16816(float* c, const uint32_t* a, uint32_t b0, uint32_t b1) {
    asm volatile("mma.sync.aligned.m16n8k16.row.col.f32.f16.f16.f32 "
        "{%0,%1,%2,%3},{%4,%5,%6,%7},{%8,%9},{%0,%1,%2,%3};"
        : "+f"(c[0]), "+f"(c[1]), "+f"(c[2]), "+f"(c[3])
        : "r"(a[0]), "r"(a[1]), "r"(a[2]), "r"(a[3]), "r"(b0), "r"(b1));
}

__device__ __forceinline__ void store_h2(__half* dst, size_t off, float v0, float v1) {
    *(__half2*)(dst + off) = __floats2half2_rn(v0, v1);
}

union H4 { uint2 u; __half2 p[2]; };

__device__ __forceinline__ void wsplit4(const float* v, H4& hv, H4& lv) {
    __half h0 = __float2half_rn(v[0]);
    __half h1 = __float2half_rn(v[1]);
    __half h2 = __float2half_rn(v[2]);
    __half h3 = __float2half_rn(v[3]);
    hv.p[0] = __halves2half2(h0, h1);
    hv.p[1] = __halves2half2(h2, h3);
    lv.p[0] = __halves2half2(__float2half_rn(v[0] - __half2float(h0)),
                             __float2half_rn(v[1] - __half2float(h1)));
    lv.p[1] = __halves2half2(__float2half_rn(v[2] - __half2float(h2)),
                             __float2half_rn(v[3] - __half2float(h3)));
}

// ---------------- kernel: extract diagonal blocks -> fp16 (4 elems/thread) ----------------
__global__ void extract_kernel(const float* __restrict__ x) {
    int q = blockIdx.x * blockDim.x + threadIdx.x;        // quad index
    if (q >= ROWS * KPAD1 / 4) return;
    int f0 = (q % (KPAD1 / 4)) * 4;
    int sb = q / (KPAD1 / 4);
    int b  = sb & (BATCH - 1);
    int s  = sb >> 8;
    const float* xb = x + (size_t)b * (TOTAL_R * TOTAL_R);
    float v[4];
    #pragma unroll
    for (int e = 0; e < 4; e++) {
        int f = f0 + e;
        float vv = 0.f;
        if (f < FLAT) {
            int i = f / REGIONS;
            int j = f - i * REGIONS;
            vv = xb[(s * REGIONS + i) * TOTAL_R + (s * REGIONS + j)];
        }
        v[e] = vv;
    }
    H4 hv;
    hv.p[0] = __floats2half2_rn(v[0], v[1]);
    hv.p[1] = __floats2half2_rn(v[2], v[3]);
    *(uint2*)(g_flat + (size_t)sb * KPAD1 + f0) = hv.u;
}

// ---------------- W1 transpose: [s][2500][512] -> [s][512][2560] single fp16 ----------------
__global__ void wconv_w1_kernel(const float* __restrict__ src) {
    __shared__ float tile[32][33];
    int k0 = blockIdx.x * 32, n0 = blockIdx.y * 32, z = blockIdx.z;
    const float* sp = src + (size_t)z * FLAT * HIDDEN;
    size_t dbase = (size_t)z * HIDDEN * KPAD1;
    int tid = threadIdx.x;
    int tx = tid & 31, ty = tid >> 5;       // 256 threads
    #pragma unroll
    for (int r = 0; r < 4; r++) {
        int k = k0 + ty + r * 8;
        tile[ty + r * 8][tx] = (k < FLAT) ? sp[(size_t)k * HIDDEN + n0 + tx] : 0.f;
    }
    __syncthreads();
    int n = tid >> 3, kq = (tid & 7) * 4;
    H4 hv;
    hv.p[0] = __floats2half2_rn(tile[kq][n],     tile[kq + 1][n]);
    hv.p[1] = __floats2half2_rn(tile[kq + 2][n], tile[kq + 3][n]);
    *(uint2*)(g_W1T_hi + dbase + (size_t)(n0 + n) * KPAD1 + k0 + kq) = hv.u;
}

// ---------------- batched 512x512 transpose+split (13 slices, one launch) ----------------
struct W13 {
    const float* src[13];
    __half* dhi[13];
    __half* dlo[13];
};
__global__ void wconv512_kernel(W13 a) {
    __shared__ float tile[32][33];
    int z = blockIdx.z;
    const float* sp = a.src[z];
    __half* dhi = a.dhi[z];
    __half* dlo = a.dlo[z];
    int k0 = blockIdx.x * 32, n0 = blockIdx.y * 32;
    int tid = threadIdx.x;
    int tx = tid & 31, ty = tid >> 5;
    #pragma unroll
    for (int r = 0; r < 4; r++) {
        int k = k0 + ty + r * 8;
        tile[ty + r * 8][tx] = sp[(size_t)k * HIDDEN + n0 + tx];
    }
    __syncthreads();
    int n = tid >> 3, kq = (tid & 7) * 4;
    float v[4];
    #pragma unroll
    for (int i = 0; i < 4; i++) v[i] = tile[kq + i][n];
    H4 hv, lv; wsplit4(v, hv, lv);
    size_t off = (size_t)(n0 + n) * HIDDEN + k0 + kq;
    *(uint2*)(dhi + off) = hv.u;
    *(uint2*)(dlo + off) = lv.u;
}

// ---------------- mma.sync GEMM: C[2048][N] = A[2048][K] * W^T + epilogue ----------------
// TERMS=2: C = A*Wh + A*Wl; TERMS=1: C = A*Wh. fp32 accum. BM=BN=64, BK=64,
// 4-stage cp.async pipeline, 8 warps (wm 2)x(wn 2)x(wk 2), warp tile 32x32,
// K split across wk + SMEM reduce. MMAs term-major.
// EP: 0 relu->fp16 | 1 f32 | 2 qkv split f32 | 3 fp16 | 4 resid+permute f32
template<int EP, int TERMS>
__global__ __launch_bounds__(256, 2) void tc_gemm(
    const __half* __restrict__ A, int sA,
    const __half* __restrict__ Bhi, const __half* __restrict__ Blo, int sB,
    long bSub, int Ksteps,
    const float* __restrict__ bias,
    float* __restrict__ o32,
    __half* __restrict__ oH,
    const float* __restrict__ resid,
    float* __restrict__ oq, float* __restrict__ okk, float* __restrict__ ov,
    const float* __restrict__ bq, const float* __restrict__ bk, const float* __restrict__ bv)
{
    constexpr uint32_t STG = (TERMS + 1) * T_BYTES;   // A + TERMS B tiles
    extern __shared__ __align__(128) char smem[];
    const uint32_t sbase = smem_u32(smem);
    const int tid = threadIdx.x;
    const int mBase = blockIdx.y * BM;
    const int nBase = blockIdx.x * BN;
    const int sIdx = blockIdx.y >> 2;        // 4 M-tiles (256 rows) per subnet

    const __half* aP = A + (size_t)mBase * sA;
    size_t boff = (bSub > 0 ? (size_t)sIdx * (size_t)bSub : 0) + (size_t)nBase * sB;
    const __half* bH = Bhi + boff;
    const __half* bL = Blo + boff;
    const float* biasP = bias ? (bias + (bSub > 0 ? sIdx * HIDDEN : 0)) : bias;

    // ---- async-copy one K-chunk; ALWAYS commits exactly one group ----
    auto issue = [&](int chunk) {
        if (chunk < Ksteps) {
            const uint32_t st = sbase + (chunk % NSTAGE) * STG;
            const int k0 = chunk * BK;
            #pragma unroll
            for (int i = 0; i < 2; i++) {
                int idx = tid + i * 256;
                int row = idx >> 3, c = idx & 7;
                cpa16(st + row * ASTRIDE + c * 16, aP + (size_t)row * sA + k0 + c * 8);
            }
            #pragma unroll
            for (int i = 0; i < 2; i++) {
                int idx = tid + i * 256;
                int row = idx >> 3, c = idx & 7;
                uint32_t so = st + T_BYTES + row * ASTRIDE + c * 16;
                cpa16(so, bH + (size_t)row * sB + k0 + c * 8);
                if (TERMS == 2)
                    cpa16(so + T_BYTES, bL + (size_t)row * sB + k0 + c * 8);
            }
        }
        cpa_commit();
    };

    issue(0); issue(1); issue(2);

    const int wid = tid >> 5, lane = tid & 31;
    const int wk = wid >> 2;                 // 0/1 : handles kk = 2*wk + {0,1}
    const int wm = (wid >> 1) & 1;           // 32-row half
    const int wn = wid & 1;                  // 32-col half
    const uint32_t lrow = lane & 15;
    const uint32_t lcol = (lane >> 4) * 16;

    float acc[2][4][4];                      // [m16 tile][n8 tile][frag]
    #pragma unroll
    for (int i = 0; i < 2; i++)
        #pragma unroll
        for (int j = 0; j < 4; j++)
            #pragma unroll
            for (int t = 0; t < 4; t++) acc[i][j][t] = 0.f;

    for (int s = 0; s < Ksteps; ++s) {
        cpa_wait<2>();                 // stage s landed (3 in flight)
        __syncthreads();               // all warps done with buffer (s-1)%4
        issue(s + 3);                  // refill freed buffer, overlaps compute
        const uint32_t st = sbase + (s % NSTAGE) * STG;
        #pragma unroll
        for (int j = 0; j < 2; ++j) {
            const int kk = wk * 2 + j;
            uint32_t aF[2][4], bHf[2][4], bLf[2][4];
            #pragma unroll
            for (int am = 0; am < 2; am++) {
                uint32_t ad = st + (wm * 32 + am * 16 + lrow) * ASTRIDE + kk * 32 + lcol;
                ldm4(ad, aF[am]);
            }
            #pragma unroll
            for (int bt = 0; bt < 2; bt++) {
                uint32_t bd = st + T_BYTES + (wn * 32 + bt * 16 + lrow) * ASTRIDE + kk * 32 + lcol;
                ldm4(bd, bHf[bt]);
                if (TERMS == 2) ldm4(bd + T_BYTES, bLf[bt]);
            }
            // term-major: acc reuse distance 8
            #pragma unroll
            for (int am = 0; am < 2; am++)
                #pragma unroll
                for (int bt = 0; bt < 2; bt++) {
                    mma16816(acc[am][2*bt],   aF[am], bHf[bt][0], bHf[bt][2]);
                    mma16816(acc[am][2*bt+1], aF[am], bHf[bt][1], bHf[bt][3]);
                }
            if (TERMS == 2) {
                #pragma unroll
                for (int am = 0; am < 2; am++)
                    #pragma unroll
                    for (int bt = 0; bt < 2; bt++) {
                        mma16816(acc[am][2*bt],   aF[am], bLf[bt][0], bLf[bt][2]);
                        mma16816(acc[am][2*bt+1], aF[am], bLf[bt][1], bLf[bt][3]);
                    }
            }
        }
    }

    // ---- reduce wk=1 partial sums into wk=0 via SMEM (stages are dead now) ----
    __syncthreads();
    float* red = (float*)smem;               // 4 regions of [32][34] floats
    float* rbase = red + (wm * 2 + wn) * (32 * 34);
    if (wk == 1) {
        #pragma unroll
        for (int am = 0; am < 2; am++)
            #pragma unroll
            for (int an = 0; an < 4; an++)
                #pragma unroll
                for (int t = 0; t < 4; t++) {
                    int row = am * 16 + (lane >> 2) + (t >> 1) * 8;
                    int col = an * 8 + (lane & 3) * 2 + (t & 1);
                    rbase[row * 34 + col] = acc[am][an][t];
                }
    }
    __syncthreads();
    if (wk == 1) return;
    #pragma unroll
    for (int am = 0; am < 2; am++)
        #pragma unroll
        for (int an = 0; an < 4; an++)
            #pragma unroll
            for (int t = 0; t < 4; t++) {
                int row = am * 16 + (lane >> 2) + (t >> 1) * 8;
                int col = an * 8 + (lane & 3) * 2 + (t & 1);
                acc[am][an][t] += rbase[row * 34 + col];
            }

    // ---- epilogue (wk=0 warps only): registers -> global ----
    #pragma unroll
    for (int am = 0; am < 2; am++) {
        #pragma unroll
        for (int an = 0; an < 4; an++) {
            int m0 = mBase + wm * 32 + am * 16 + (lane >> 2);
            int g  = nBase + wn * 32 + an * 8 + (lane & 3) * 2;
            #pragma unroll
            for (int half = 0; half < 2; half++) {
                int m = m0 + half * 8;
                float v0 = acc[am][an][half * 2];
                float v1 = acc[am][an][half * 2 + 1];
                if (EP == 0) {                          // relu -> fp16
                    v0 = fmaxf(v0 + biasP[g], 0.f);
                    v1 = fmaxf(v1 + biasP[g + 1], 0.f);
                    store_h2(oH, (size_t)m * HIDDEN + g, v0, v1);
                } else if (EP == 1) {                   // xsub fp32
                    v0 += biasP[g]; v1 += biasP[g + 1];
                    *(float2*)(o32 + (size_t)m * HIDDEN + g) = make_float2(v0, v1);
                } else if (EP == 2) {                   // qkv fp32 split
                    int which = g >> 9, lc = g & 511;
                    const float* bb = (which == 0) ? bq : (which == 1) ? bk : bv;
                    float* dst = (which == 0) ? oq : (which == 1) ? okk : ov;
                    v0 += bb[lc]; v1 += bb[lc + 1];
                    *(float2*)(dst + (size_t)m * HIDDEN + lc) = make_float2(v0, v1);
                } else if (EP == 3) {                   // fp16 out (t)
                    v0 += biasP[g]; v1 += biasP[g + 1];
                    store_h2(oH, (size_t)m * HIDDEN + g, v0, v1);
                } else {                                // out = . + bp + xsub, (b,s) order
                    v0 += biasP[g] + resid[(size_t)m * HIDDEN + g];
                    v1 += biasP[g + 1] + resid[(size_t)m * HIDDEN + g + 1];
                    int bb2 = m & (BATCH - 1), ss = m >> 8;
                    *(float2*)(o32 + ((size_t)((bb2 << 3) + ss)) * HIDDEN + g) = make_float2(v0, v1);
                }
            }
        }
    }
}

// ---------------- LayerNorm: xsub fp32 -> xn fp16 ----------------
__global__ __launch_bounds__(256) void ln_kernel(const float* __restrict__ lng,
                                                 const float* __restrict__ lnb)
{
    int r = blockIdx.x, t = threadIdx.x;
    const float* xs = g_xsub + (size_t)r * HIDDEN;
    float v0 = xs[t], v1 = xs[t + 256];
    float s = v0 + v1, q = v0 * v0 + v1 * v1;
    #pragma unroll
    for (int o = 16; o > 0; o >>= 1) {
        s += __shfl_xor_sync(0xFFFFFFFFu, s, o);
        q += __shfl_xor_sync(0xFFFFFFFFu, q, o);
    }
    __shared__ float ss[8], sq[8];
    int w = t >> 5, l = t & 31;
    if (l == 0) { ss[w] = s; sq[w] = q; }
    __syncthreads();
    if (w == 0) {
        float a = (l < 8) ? ss[l] : 0.f;
        float c = (l < 8) ? sq[l] : 0.f;
        #pragma unroll
        for (int o = 4; o > 0; o >>= 1) {
            a += __shfl_xor_sync(0xFFFFFFFFu, a, o);
            c += __shfl_xor_sync(0xFFFFFFFFu, c, o);
        }
        if (l == 0) { ss[0] = a; sq[0] = c; }
    }
    __syncthreads();
    float mean = ss[0] * (1.f / HIDDEN);
    float var  = sq[0] * (1.f / HIDDEN) - mean * mean;
    float inv  = rsqrtf(var + LN_EPS);
    float o0 = (v0 - mean) * inv * lng[t] + lnb[t];
    float o1 = (v1 - mean) * inv * lng[t + 256] + lnb[t + 256];
    size_t base = (size_t)r * HIDDEN;
    g_xn[base + t]       = __float2half_rn(o0);
    g_xn[base + t + 256] = __float2half_rn(o1);
}

// ---------------- attention: q,k,v fp32 -> ctx fp16 ----------------
__global__ __launch_bounds__(256) void attn_kernel()
{
    __shared__ float q_s[NUM_SUBNETS][520];
    __shared__ float k_s[NUM_SUBNETS][520];
    __shared__ float sc[HEADS][NUM_SUBNETS][NUM_SUBNETS];

    int b = blockIdx.x;
    int tid = threadIdx.x;

    for (int i = tid; i < NUM_SUBNETS * HIDDEN; i += 256) {
        int m = i >> 9, c = i & 511;
        size_t gi = ((size_t)(m * BATCH + b)) * HIDDEN + c;
        q_s[m][c] = g_q[gi];
        k_s[m][c] = g_k[gi];
    }
    __syncthreads();

    int h = tid >> 5, l = tid & 31;

    #pragma unroll
    for (int pp = 0; pp < 2; pp++) {
        int p = l + pp * 32;
        int m = p >> 3, n = p & 7;
        const float* qp = &q_s[m][h * HEAD_DIM];
        const float* kp = &k_s[n][h * HEAD_DIM];
        float sv = 0.f;
        #pragma unroll
        for (int d = 0; d < HEAD_DIM; d++) sv += qp[d] * kp[d];
        sv *= 0.125f;
        sc[h][m][n] = (m == n) ? 0.f : sv;
    }
    __syncwarp();

    if (l < NUM_SUBNETS) {
        float mx = -1e30f;
        #pragma unroll
        for (int n = 0; n < 8; n++) mx = fmaxf(mx, sc[h][l][n]);
        float e[8], sum = 0.f;
        #pragma unroll
        for (int n = 0; n < 8; n++) { e[n] = expf(sc[h][l][n] - mx); sum += e[n]; }
        float inv = 1.f / sum;
        #pragma unroll
        for (int n = 0; n < 8; n++) sc[h][l][n] = e[n] * inv;
    }
    __syncwarp();

    #pragma unroll
    for (int dd = 0; dd < 2; dd++) {
        int d = l + dd * 32;
        float vv[8];
        #pragma unroll
        for (int n = 0; n < 8; n++)
            vv[n] = g_v[((size_t)(n * BATCH + b)) * HIDDEN + h * HEAD_DIM + d];
        #pragma unroll
        for (int m = 0; m < 8; m++) {
            float cv = 0.f;
            #pragma unroll
            for (int n = 0; n < 8; n++) cv += sc[h][m][n] * vv[n];
            g_ctx[((size_t)(m * BATCH + b)) * HIDDEN + h * HEAD_DIM + d] = __float2half_rn(cv);
        }
    }
}

// ---------------- launch ----------------
extern "C" void kernel_launch(void* const* d_in, const int* in_sizes, int n_in,
                              void* d_out, int out_size)
{
    (void)in_sizes; (void)n_in; (void)out_size;
    const float* x    = (const float*)d_in[0];
    const float* W1   = (const float*)d_in[2];
    const float* b1   = (const float*)d_in[3];
    const float* W2   = (const float*)d_in[4];
    const float* b2   = (const float*)d_in[5];
    const float* ln_g = (const float*)d_in[6];
    const float* ln_b = (const float*)d_in[7];
    const float* Wq   = (const float*)d_in[8];
    const float* bq   = (const float*)d_in[9];
    const float* Wk   = (const float*)d_in[10];
    const float* bk   = (const float*)d_in[11];
    const float* Wv   = (const float*)d_in[12];
    const float* bv   = (const float*)d_in[13];
    const float* Wo   = (const float*)d_in[14];
    const float* bo   = (const float*)d_in[15];
    const float* Wp   = (const float*)d_in[16];
    const float* bp   = (const float*)d_in[17];
    float* out = (float*)d_out;

    __half *flat, *W1T_hi, *W2T_hi, *W2T_lo;
    __half *WqkvT_hi, *WqkvT_lo, *WoT_hi, *WoT_lo, *WpT_hi, *WpT_lo;
    __half *h, *xn, *ctx, *t;
    float *xsub, *pq, *pk, *pv;
    cudaGetSymbolAddress((void**)&flat,    g_flat);
    cudaGetSymbolAddress((void**)&W1T_hi,  g_W1T_hi);
    cudaGetSymbolAddress((void**)&W2T_hi,  g_W2T_hi);
    cudaGetSymbolAddress((void**)&W2T_lo,  g_W2T_lo);
    cudaGetSymbolAddress((void**)&WqkvT_hi, g_WqkvT_hi);
    cudaGetSymbolAddress((void**)&WqkvT_lo, g_WqkvT_lo);
    cudaGetSymbolAddress((void**)&WoT_hi,  g_WoT_hi);
    cudaGetSymbolAddress((void**)&WoT_lo,  g_WoT_lo);
    cudaGetSymbolAddress((void**)&WpT_hi,  g_WpT_hi);
    cudaGetSymbolAddress((void**)&WpT_lo,  g_WpT_lo);
    cudaGetSymbolAddress((void**)&h,       g_h);
    cudaGetSymbolAddress((void**)&xn,      g_xn);
    cudaGetSymbolAddress((void**)&ctx,     g_ctx);
    cudaGetSymbolAddress((void**)&t,       g_t);
    cudaGetSymbolAddress((void**)&xsub,    g_xsub);
    cudaGetSymbolAddress((void**)&pq,      g_q);
    cudaGetSymbolAddress((void**)&pk,      g_k);
    cudaGetSymbolAddress((void**)&pv,      g_v);

    const int SMEM1 = NSTAGE * 2 * T_BYTES;   // TERMS=1: 73728
    const int SMEM2 = NSTAGE * 3 * T_BYTES;   // TERMS=2: 110592
    cudaFuncSetAttribute((const void*)tc_gemm<0,1>, cudaFuncAttributeMaxDynamicSharedMemorySize, SMEM1);
    cudaFuncSetAttribute((const void*)tc_gemm<1,2>, cudaFuncAttributeMaxDynamicSharedMemorySize, SMEM2);
    cudaFuncSetAttribute((const void*)tc_gemm<2,2>, cudaFuncAttributeMaxDynamicSharedMemorySize, SMEM2);
    cudaFuncSetAttribute((const void*)tc_gemm<3,2>, cudaFuncAttributeMaxDynamicSharedMemorySize, SMEM2);
    cudaFuncSetAttribute((const void*)tc_gemm<4,2>, cudaFuncAttributeMaxDynamicSharedMemorySize, SMEM2);

    // ---- input conversions ----
    extract_kernel<<<(ROWS * KPAD1 / 4 + 255) / 256, 256>>>(x);
    wconv_w1_kernel<<<dim3(KPAD1 / 32, HIDDEN / 32, NUM_SUBNETS), 256>>>(W1);

    W13 wa;
    for (int z = 0; z < 8; z++) {
        wa.src[z] = W2 + (size_t)z * HIDDEN * HIDDEN;
        wa.dhi[z] = W2T_hi + (size_t)z * HIDDEN * HIDDEN;
        wa.dlo[z] = W2T_lo + (size_t)z * HIDDEN * HIDDEN;
    }
    const float* srcs[5] = { Wq, Wk, Wv, Wo, Wp };
    __half* dhis[5] = { WqkvT_hi, WqkvT_hi + 512 * 512, WqkvT_hi + 1024 * 512, WoT_hi, WpT_hi };
    __half* dlos[5] = { WqkvT_lo, WqkvT_lo + 512 * 512, WqkvT_lo + 1024 * 512, WoT_lo, WpT_lo };
    for (int z = 0; z < 5; z++) {
        wa.src[8 + z] = srcs[z];
        wa.dhi[8 + z] = dhis[z];
        wa.dlo[8 + z] = dlos[z];
    }
    wconv512_kernel<<<dim3(16, 16, 13), 256>>>(wa);

    dim3 g512(HIDDEN / BN, ROWS / BM);        // 8 x 32 = 256 CTAs
    dim3 gqkv(3 * HIDDEN / BN, ROWS / BM);    // 24 x 32 = 768 CTAs

    // GEMM1: h = relu(flat @ W1 + b1) -> fp16   (single-term weights)
    tc_gemm<0,1><<<g512, 256, SMEM1>>>(flat, KPAD1, W1T_hi, W1T_hi, KPAD1,
        (long)HIDDEN * KPAD1, KPAD1 / BK, b1, nullptr, h,
        nullptr, nullptr, nullptr, nullptr, nullptr, nullptr, nullptr);
    // GEMM2: xsub = h @ W2 + b2 (fp32)
    tc_gemm<1,2><<<g512, 256, SMEM2>>>(h, HIDDEN, W2T_hi, W2T_lo, HIDDEN,
        (long)HIDDEN * HIDDEN, HIDDEN / BK, b2, xsub, nullptr,
        nullptr, nullptr, nullptr, nullptr, nullptr, nullptr, nullptr);
    // LN -> xn fp16
    ln_kernel<<<ROWS, 256>>>(ln_g, ln_b);
    // QKV fused (fp32 outputs)
    tc_gemm<2,2><<<gqkv, 256, SMEM2>>>(xn, HIDDEN, WqkvT_hi, WqkvT_lo, HIDDEN,
        0L, HIDDEN / BK, nullptr, nullptr, nullptr,
        nullptr, pq, pk, pv, bq, bk, bv);
    // attention -> ctx fp16
    attn_kernel<<<BATCH, 256>>>();
    // O: t = ctx @ Wo + bo -> fp16
    tc_gemm<3,2><<<g512, 256, SMEM2>>>(ctx, HIDDEN, WoT_hi, WoT_lo, HIDDEN,
        0L, HIDDEN / BK, bo, nullptr, t,
        nullptr, nullptr, nullptr, nullptr, nullptr, nullptr, nullptr);
    // P: out = t @ Wp + bp + xsub (permuted to (b,s))
    tc_gemm<4,2><<<g512, 256, SMEM2>>>(t, HIDDEN, WpT_hi, WpT_lo, HIDDEN,
        0L, HIDDEN / BK, bp, out, nullptr,
        xsub, nullptr, nullptr, nullptr, nullptr, nullptr, nullptr);
}

// round 10
// speedup vs baseline: 1.6746x; 1.1366x over previous
#include <cuda_runtime.h>
#include <cuda_fp16.h>
#include <math.h>
#include <cstdint>

// ---------------- problem constants ----------------
#define NUM_SUBNETS 8
#define REGIONS     50
#define TOTAL_R     400
#define HIDDEN      512
#define HEADS       8
#define HEAD_DIM    64
#define BATCH       256
#define FLAT        2500
#define ROWS        (NUM_SUBNETS * BATCH)   // 2048
#define LN_EPS      1e-5f
#define KPAD1       2560                    // FLAT padded to multiple of 64

// GEMM tiling: A single fp16; W either single fp16 (TERMS=1) or split hi/lo (TERMS=2).
#define BM 64
#define BN 64
#define BK 64
#define ASTRIDE 144                         // bytes per 64-col fp16 row (128 + 16 pad)
#define T_BYTES (BM * ASTRIDE)              // 9216 per tile array
#define NSTAGE  4

typedef unsigned long long u64;

// ---------------- scratch (device globals) ----------------
__device__ __half g_flat[ROWS * KPAD1];
__device__ __half g_W1T_hi[NUM_SUBNETS * HIDDEN * KPAD1];
__device__ __half g_W2T_hi[NUM_SUBNETS * HIDDEN * HIDDEN];
__device__ __half g_W2T_lo[NUM_SUBNETS * HIDDEN * HIDDEN];
__device__ __half g_WqkvT_hi[3 * HIDDEN * HIDDEN];
__device__ __half g_WoT_hi[HIDDEN * HIDDEN];
__device__ __half g_WpT_hi[HIDDEN * HIDDEN];

__device__ __half g_h  [ROWS * HIDDEN];
__device__ float  g_xsub[ROWS * HIDDEN];
__device__ __half g_xn [ROWS * HIDDEN];
__device__ float  g_q  [ROWS * HIDDEN];
__device__ float  g_k  [ROWS * HIDDEN];
__device__ float  g_v  [ROWS * HIDDEN];
__device__ __half g_ctx[ROWS * HIDDEN];
__device__ __half g_t  [ROWS * HIDDEN];

// ---------------- PTX helpers (sm_80-ratified only) ----------------
__device__ __forceinline__ uint32_t smem_u32(const void* p) {
    uint32_t a;
    asm("{ .reg .u64 t; cvta.to.shared.u64 t, %1; cvt.u32.u64 %0, t; }" : "=r"(a) : "l"(p));
    return a;
}
__device__ __forceinline__ void cpa16(uint32_t s, const void* g) {
    asm volatile("cp.async.cg.shared.global [%0], [%1], 16;" :: "r"(s), "l"(g));
}
__device__ __forceinline__ void cpa_commit() {
    asm volatile("cp.async.commit_group;" ::: "memory");
}
template<int N> __device__ __forceinline__ void cpa_wait() {
    asm volatile("cp.async.wait_group %0;" :: "n"(N) : "memory");
}
__device__ __forceinline__ void ldm4(uint32_t a, uint32_t* r) {
    asm volatile("ldmatrix.sync.aligned.m8n8.x4.shared.b16 {%0,%1,%2,%3}, [%4];"
        : "=r"(r[0]), "=r"(r[1]), "=r"(r[2]), "=r"(r[3]) : "r"(a));
}
__device__ __forceinline__ void mma16816(float* c, const uint32_t* a, uint32_t b0, uint32_t b1) {
    asm volatile("mma.sync.aligned.m16n8k16.row.col.f32.f16.f16.f32 "
        "{%0,%1,%2,%3},{%4,%5,%6,%7},{%8,%9},{%0,%1,%2,%3};"
        : "+f"(c[0]), "+f"(c[1]), "+f"(c[2]), "+f"(c[3])
        : "r"(a[0]), "r"(a[1]), "r"(a[2]), "r"(a[3]), "r"(b0), "r"(b1));
}

__device__ __forceinline__ void store_h2(__half* dst, size_t off, float v0, float v1) {
    *(__half2*)(dst + off) = __floats2half2_rn(v0, v1);
}

union H4 { uint2 u; __half2 p[2]; };

__device__ __forceinline__ void wsplit4(const float* v, H4& hv, H4& lv) {
    __half h0 = __float2half_rn(v[0]);
    __half h1 = __float2half_rn(v[1]);
    __half h2 = __float2half_rn(v[2]);
    __half h3 = __float2half_rn(v[3]);
    hv.p[0] = __halves2half2(h0, h1);
    hv.p[1] = __halves2half2(h2, h3);
    lv.p[0] = __halves2half2(__float2half_rn(v[0] - __half2float(h0)),
                             __float2half_rn(v[1] - __half2float(h1)));
    lv.p[1] = __halves2half2(__float2half_rn(v[2] - __half2float(h2)),
                             __float2half_rn(v[3] - __half2float(h3)));
}

// ---------------- kernel: extract diagonal blocks -> fp16 (4 elems/thread) ----------------
__global__ void extract_kernel(const float* __restrict__ x) {
    int q = blockIdx.x * blockDim.x + threadIdx.x;        // quad index
    if (q >= ROWS * KPAD1 / 4) return;
    int f0 = (q % (KPAD1 / 4)) * 4;
    int sb = q / (KPAD1 / 4);
    int b  = sb & (BATCH - 1);
    int s  = sb >> 8;
    const float* xb = x + (size_t)b * (TOTAL_R * TOTAL_R);
    float v[4];
    #pragma unroll
    for (int e = 0; e < 4; e++) {
        int f = f0 + e;
        float vv = 0.f;
        if (f < FLAT) {
            int i = f / REGIONS;
            int j = f - i * REGIONS;
            vv = xb[(s * REGIONS + i) * TOTAL_R + (s * REGIONS + j)];
        }
        v[e] = vv;
    }
    H4 hv;
    hv.p[0] = __floats2half2_rn(v[0], v[1]);
    hv.p[1] = __floats2half2_rn(v[2], v[3]);
    *(uint2*)(g_flat + (size_t)sb * KPAD1 + f0) = hv.u;
}

// ---------------- W1 transpose: [s][2500][512] -> [s][512][2560] single fp16 ----------------
__global__ void wconv_w1_kernel(const float* __restrict__ src) {
    __shared__ float tile[32][33];
    int k0 = blockIdx.x * 32, n0 = blockIdx.y * 32, z = blockIdx.z;
    const float* sp = src + (size_t)z * FLAT * HIDDEN;
    size_t dbase = (size_t)z * HIDDEN * KPAD1;
    int tid = threadIdx.x;
    int tx = tid & 31, ty = tid >> 5;       // 256 threads
    #pragma unroll
    for (int r = 0; r < 4; r++) {
        int k = k0 + ty + r * 8;
        tile[ty + r * 8][tx] = (k < FLAT) ? sp[(size_t)k * HIDDEN + n0 + tx] : 0.f;
    }
    __syncthreads();
    int n = tid >> 3, kq = (tid & 7) * 4;
    H4 hv;
    hv.p[0] = __floats2half2_rn(tile[kq][n],     tile[kq + 1][n]);
    hv.p[1] = __floats2half2_rn(tile[kq + 2][n], tile[kq + 3][n]);
    *(uint2*)(g_W1T_hi + dbase + (size_t)(n0 + n) * KPAD1 + k0 + kq) = hv.u;
}

// ---------------- batched 512x512 transpose (+ optional lo split), one launch ----------------
struct W13 {
    const float* src[13];
    __half* dhi[13];
    __half* dlo[13];    // nullptr -> single-term slice (no lo plane)
};
__global__ void wconv512_kernel(W13 a) {
    __shared__ float tile[32][33];
    int z = blockIdx.z;
    const float* sp = a.src[z];
    __half* dhi = a.dhi[z];
    __half* dlo = a.dlo[z];
    int k0 = blockIdx.x * 32, n0 = blockIdx.y * 32;
    int tid = threadIdx.x;
    int tx = tid & 31, ty = tid >> 5;
    #pragma unroll
    for (int r = 0; r < 4; r++) {
        int k = k0 + ty + r * 8;
        tile[ty + r * 8][tx] = sp[(size_t)k * HIDDEN + n0 + tx];
    }
    __syncthreads();
    int n = tid >> 3, kq = (tid & 7) * 4;
    float v[4];
    #pragma unroll
    for (int i = 0; i < 4; i++) v[i] = tile[kq + i][n];
    size_t off = (size_t)(n0 + n) * HIDDEN + k0 + kq;
    if (dlo) {
        H4 hv, lv; wsplit4(v, hv, lv);
        *(uint2*)(dhi + off) = hv.u;
        *(uint2*)(dlo + off) = lv.u;
    } else {
        H4 hv;
        hv.p[0] = __floats2half2_rn(v[0], v[1]);
        hv.p[1] = __floats2half2_rn(v[2], v[3]);
        *(uint2*)(dhi + off) = hv.u;
    }
}

// ---------------- mma.sync GEMM: C[2048][N] = A[2048][K] * W^T + epilogue ----------------
// TERMS=2: C = A*Wh + A*Wl; TERMS=1: C = A*Wh. fp32 accum. BM=BN=64, BK=64,
// 4-stage cp.async pipeline, 8 warps (wm 2)x(wn 2)x(wk 2), warp tile 32x32,
// K split across wk + SMEM reduce. MMAs term-major.
// EP: 0 relu->fp16 | 1 f32 | 2 qkv split f32 | 3 fp16 | 4 resid+permute f32
template<int EP, int TERMS>
__global__ __launch_bounds__(256, 2) void tc_gemm(
    const __half* __restrict__ A, int sA,
    const __half* __restrict__ Bhi, const __half* __restrict__ Blo, int sB,
    long bSub, int Ksteps,
    const float* __restrict__ bias,
    float* __restrict__ o32,
    __half* __restrict__ oH,
    const float* __restrict__ resid,
    float* __restrict__ oq, float* __restrict__ okk, float* __restrict__ ov,
    const float* __restrict__ bq, const float* __restrict__ bk, const float* __restrict__ bv)
{
    constexpr uint32_t STG = (TERMS + 1) * T_BYTES;   // A + TERMS B tiles
    extern __shared__ __align__(128) char smem[];
    const uint32_t sbase = smem_u32(smem);
    const int tid = threadIdx.x;
    const int mBase = blockIdx.y * BM;
    const int nBase = blockIdx.x * BN;
    const int sIdx = blockIdx.y >> 2;        // 4 M-tiles (256 rows) per subnet

    const __half* aP = A + (size_t)mBase * sA;
    size_t boff = (bSub > 0 ? (size_t)sIdx * (size_t)bSub : 0) + (size_t)nBase * sB;
    const __half* bH = Bhi + boff;
    const __half* bL = Blo + boff;
    const float* biasP = bias ? (bias + (bSub > 0 ? sIdx * HIDDEN : 0)) : bias;

    // ---- async-copy one K-chunk; ALWAYS commits exactly one group ----
    auto issue = [&](int chunk) {
        if (chunk < Ksteps) {
            const uint32_t st = sbase + (chunk % NSTAGE) * STG;
            const int k0 = chunk * BK;
            #pragma unroll
            for (int i = 0; i < 2; i++) {
                int idx = tid + i * 256;
                int row = idx >> 3, c = idx & 7;
                cpa16(st + row * ASTRIDE + c * 16, aP + (size_t)row * sA + k0 + c * 8);
            }
            #pragma unroll
            for (int i = 0; i < 2; i++) {
                int idx = tid + i * 256;
                int row = idx >> 3, c = idx & 7;
                uint32_t so = st + T_BYTES + row * ASTRIDE + c * 16;
                cpa16(so, bH + (size_t)row * sB + k0 + c * 8);
                if (TERMS == 2)
                    cpa16(so + T_BYTES, bL + (size_t)row * sB + k0 + c * 8);
            }
        }
        cpa_commit();
    };

    issue(0); issue(1); issue(2);

    const int wid = tid >> 5, lane = tid & 31;
    const int wk = wid >> 2;                 // 0/1 : handles kk = 2*wk + {0,1}
    const int wm = (wid >> 1) & 1;           // 32-row half
    const int wn = wid & 1;                  // 32-col half
    const uint32_t lrow = lane & 15;
    const uint32_t lcol = (lane >> 4) * 16;

    float acc[2][4][4];                      // [m16 tile][n8 tile][frag]
    #pragma unroll
    for (int i = 0; i < 2; i++)
        #pragma unroll
        for (int j = 0; j < 4; j++)
            #pragma unroll
            for (int t = 0; t < 4; t++) acc[i][j][t] = 0.f;

    for (int s = 0; s < Ksteps; ++s) {
        cpa_wait<2>();                 // stage s landed (3 in flight)
        __syncthreads();               // all warps done with buffer (s-1)%4
        issue(s + 3);                  // refill freed buffer, overlaps compute
        const uint32_t st = sbase + (s % NSTAGE) * STG;
        #pragma unroll
        for (int j = 0; j < 2; ++j) {
            const int kk = wk * 2 + j;
            uint32_t aF[2][4], bHf[2][4], bLf[2][4];
            #pragma unroll
            for (int am = 0; am < 2; am++) {
                uint32_t ad = st + (wm * 32 + am * 16 + lrow) * ASTRIDE + kk * 32 + lcol;
                ldm4(ad, aF[am]);
            }
            #pragma unroll
            for (int bt = 0; bt < 2; bt++) {
                uint32_t bd = st + T_BYTES + (wn * 32 + bt * 16 + lrow) * ASTRIDE + kk * 32 + lcol;
                ldm4(bd, bHf[bt]);
                if (TERMS == 2) ldm4(bd + T_BYTES, bLf[bt]);
            }
            // term-major: acc reuse distance 8
            #pragma unroll
            for (int am = 0; am < 2; am++)
                #pragma unroll
                for (int bt = 0; bt < 2; bt++) {
                    mma16816(acc[am][2*bt],   aF[am], bHf[bt][0], bHf[bt][2]);
                    mma16816(acc[am][2*bt+1], aF[am], bHf[bt][1], bHf[bt][3]);
                }
            if (TERMS == 2) {
                #pragma unroll
                for (int am = 0; am < 2; am++)
                    #pragma unroll
                    for (int bt = 0; bt < 2; bt++) {
                        mma16816(acc[am][2*bt],   aF[am], bLf[bt][0], bLf[bt][2]);
                        mma16816(acc[am][2*bt+1], aF[am], bLf[bt][1], bLf[bt][3]);
                    }
            }
        }
    }

    // ---- reduce wk=1 partial sums into wk=0 via SMEM (stages are dead now) ----
    __syncthreads();
    float* red = (float*)smem;               // 4 regions of [32][34] floats
    float* rbase = red + (wm * 2 + wn) * (32 * 34);
    if (wk == 1) {
        #pragma unroll
        for (int am = 0; am < 2; am++)
            #pragma unroll
            for (int an = 0; an < 4; an++)
                #pragma unroll
                for (int t = 0; t < 4; t++) {
                    int row = am * 16 + (lane >> 2) + (t >> 1) * 8;
                    int col = an * 8 + (lane & 3) * 2 + (t & 1);
                    rbase[row * 34 + col] = acc[am][an][t];
                }
    }
    __syncthreads();
    if (wk == 1) return;
    #pragma unroll
    for (int am = 0; am < 2; am++)
        #pragma unroll
        for (int an = 0; an < 4; an++)
            #pragma unroll
            for (int t = 0; t < 4; t++) {
                int row = am * 16 + (lane >> 2) + (t >> 1) * 8;
                int col = an * 8 + (lane & 3) * 2 + (t & 1);
                acc[am][an][t] += rbase[row * 34 + col];
            }

    // ---- epilogue (wk=0 warps only): registers -> global ----
    #pragma unroll
    for (int am = 0; am < 2; am++) {
        #pragma unroll
        for (int an = 0; an < 4; an++) {
            int m0 = mBase + wm * 32 + am * 16 + (lane >> 2);
            int g  = nBase + wn * 32 + an * 8 + (lane & 3) * 2;
            #pragma unroll
            for (int half = 0; half < 2; half++) {
                int m = m0 + half * 8;
                float v0 = acc[am][an][half * 2];
                float v1 = acc[am][an][half * 2 + 1];
                if (EP == 0) {                          // relu -> fp16
                    v0 = fmaxf(v0 + biasP[g], 0.f);
                    v1 = fmaxf(v1 + biasP[g + 1], 0.f);
                    store_h2(oH, (size_t)m * HIDDEN + g, v0, v1);
                } else if (EP == 1) {                   // xsub fp32
                    v0 += biasP[g]; v1 += biasP[g + 1];
                    *(float2*)(o32 + (size_t)m * HIDDEN + g) = make_float2(v0, v1);
                } else if (EP == 2) {                   // qkv fp32 split
                    int which = g >> 9, lc = g & 511;
                    const float* bb = (which == 0) ? bq : (which == 1) ? bk : bv;
                    float* dst = (which == 0) ? oq : (which == 1) ? okk : ov;
                    v0 += bb[lc]; v1 += bb[lc + 1];
                    *(float2*)(dst + (size_t)m * HIDDEN + lc) = make_float2(v0, v1);
                } else if (EP == 3) {                   // fp16 out (t)
                    v0 += biasP[g]; v1 += biasP[g + 1];
                    store_h2(oH, (size_t)m * HIDDEN + g, v0, v1);
                } else {                                // out = . + bp + xsub, (b,s) order
                    v0 += biasP[g] + resid[(size_t)m * HIDDEN + g];
                    v1 += biasP[g + 1] + resid[(size_t)m * HIDDEN + g + 1];
                    int bb2 = m & (BATCH - 1), ss = m >> 8;
                    *(float2*)(o32 + ((size_t)((bb2 << 3) + ss)) * HIDDEN + g) = make_float2(v0, v1);
                }
            }
        }
    }
}

// ---------------- LayerNorm: xsub fp32 -> xn fp16 ----------------
__global__ __launch_bounds__(256) void ln_kernel(const float* __restrict__ lng,
                                                 const float* __restrict__ lnb)
{
    int r = blockIdx.x, t = threadIdx.x;
    const float* xs = g_xsub + (size_t)r * HIDDEN;
    float v0 = xs[t], v1 = xs[t + 256];
    float s = v0 + v1, q = v0 * v0 + v1 * v1;
    #pragma unroll
    for (int o = 16; o > 0; o >>= 1) {
        s += __shfl_xor_sync(0xFFFFFFFFu, s, o);
        q += __shfl_xor_sync(0xFFFFFFFFu, q, o);
    }
    __shared__ float ss[8], sq[8];
    int w = t >> 5, l = t & 31;
    if (l == 0) { ss[w] = s; sq[w] = q; }
    __syncthreads();
    if (w == 0) {
        float a = (l < 8) ? ss[l] : 0.f;
        float c = (l < 8) ? sq[l] : 0.f;
        #pragma unroll
        for (int o = 4; o > 0; o >>= 1) {
            a += __shfl_xor_sync(0xFFFFFFFFu, a, o);
            c += __shfl_xor_sync(0xFFFFFFFFu, c, o);
        }
        if (l == 0) { ss[0] = a; sq[0] = c; }
    }
    __syncthreads();
    float mean = ss[0] * (1.f / HIDDEN);
    float var  = sq[0] * (1.f / HIDDEN) - mean * mean;
    float inv  = rsqrtf(var + LN_EPS);
    float o0 = (v0 - mean) * inv * lng[t] + lnb[t];
    float o1 = (v1 - mean) * inv * lng[t + 256] + lnb[t + 256];
    size_t base = (size_t)r * HIDDEN;
    g_xn[base + t]       = __float2half_rn(o0);
    g_xn[base + t + 256] = __float2half_rn(o1);
}

// ---------------- attention: q,k,v fp32 -> ctx fp16 ----------------
__global__ __launch_bounds__(256) void attn_kernel()
{
    __shared__ float q_s[NUM_SUBNETS][520];
    __shared__ float k_s[NUM_SUBNETS][520];
    __shared__ float sc[HEADS][NUM_SUBNETS][NUM_SUBNETS];

    int b = blockIdx.x;
    int tid = threadIdx.x;

    for (int i = tid; i < NUM_SUBNETS * HIDDEN; i += 256) {
        int m = i >> 9, c = i & 511;
        size_t gi = ((size_t)(m * BATCH + b)) * HIDDEN + c;
        q_s[m][c] = g_q[gi];
        k_s[m][c] = g_k[gi];
    }
    __syncthreads();

    int h = tid >> 5, l = tid & 31;

    #pragma unroll
    for (int pp = 0; pp < 2; pp++) {
        int p = l + pp * 32;
        int m = p >> 3, n = p & 7;
        const float* qp = &q_s[m][h * HEAD_DIM];
        const float* kp = &k_s[n][h * HEAD_DIM];
        float sv = 0.f;
        #pragma unroll
        for (int d = 0; d < HEAD_DIM; d++) sv += qp[d] * kp[d];
        sv *= 0.125f;
        sc[h][m][n] = (m == n) ? 0.f : sv;
    }
    __syncwarp();

    if (l < NUM_SUBNETS) {
        float mx = -1e30f;
        #pragma unroll
        for (int n = 0; n < 8; n++) mx = fmaxf(mx, sc[h][l][n]);
        float e[8], sum = 0.f;
        #pragma unroll
        for (int n = 0; n < 8; n++) { e[n] = expf(sc[h][l][n] - mx); sum += e[n]; }
        float inv = 1.f / sum;
        #pragma unroll
        for (int n = 0; n < 8; n++) sc[h][l][n] = e[n] * inv;
    }
    __syncwarp();

    #pragma unroll
    for (int dd = 0; dd < 2; dd++) {
        int d = l + dd * 32;
        float vv[8];
        #pragma unroll
        for (int n = 0; n < 8; n++)
            vv[n] = g_v[((size_t)(n * BATCH + b)) * HIDDEN + h * HEAD_DIM + d];
        #pragma unroll
        for (int m = 0; m < 8; m++) {
            float cv = 0.f;
            #pragma unroll
            for (int n = 0; n < 8; n++) cv += sc[h][m][n] * vv[n];
            g_ctx[((size_t)(m * BATCH + b)) * HIDDEN + h * HEAD_DIM + d] = __float2half_rn(cv);
        }
    }
}

// ---------------- launch ----------------
extern "C" void kernel_launch(void* const* d_in, const int* in_sizes, int n_in,
                              void* d_out, int out_size)
{
    (void)in_sizes; (void)n_in; (void)out_size;
    const float* x    = (const float*)d_in[0];
    const float* W1   = (const float*)d_in[2];
    const float* b1   = (const float*)d_in[3];
    const float* W2   = (const float*)d_in[4];
    const float* b2   = (const float*)d_in[5];
    const float* ln_g = (const float*)d_in[6];
    const float* ln_b = (const float*)d_in[7];
    const float* Wq   = (const float*)d_in[8];
    const float* bq   = (const float*)d_in[9];
    const float* Wk   = (const float*)d_in[10];
    const float* bk   = (const float*)d_in[11];
    const float* Wv   = (const float*)d_in[12];
    const float* bv   = (const float*)d_in[13];
    const float* Wo   = (const float*)d_in[14];
    const float* bo   = (const float*)d_in[15];
    const float* Wp   = (const float*)d_in[16];
    const float* bp   = (const float*)d_in[17];
    float* out = (float*)d_out;

    __half *flat, *W1T_hi, *W2T_hi, *W2T_lo, *WqkvT_hi, *WoT_hi, *WpT_hi;
    __half *h, *xn, *ctx, *t;
    float *xsub, *pq, *pk, *pv;
    cudaGetSymbolAddress((void**)&flat,    g_flat);
    cudaGetSymbolAddress((void**)&W1T_hi,  g_W1T_hi);
    cudaGetSymbolAddress((void**)&W2T_hi,  g_W2T_hi);
    cudaGetSymbolAddress((void**)&W2T_lo,  g_W2T_lo);
    cudaGetSymbolAddress((void**)&WqkvT_hi, g_WqkvT_hi);
    cudaGetSymbolAddress((void**)&WoT_hi,  g_WoT_hi);
    cudaGetSymbolAddress((void**)&WpT_hi,  g_WpT_hi);
    cudaGetSymbolAddress((void**)&h,       g_h);
    cudaGetSymbolAddress((void**)&xn,      g_xn);
    cudaGetSymbolAddress((void**)&ctx,     g_ctx);
    cudaGetSymbolAddress((void**)&t,       g_t);
    cudaGetSymbolAddress((void**)&xsub,    g_xsub);
    cudaGetSymbolAddress((void**)&pq,      g_q);
    cudaGetSymbolAddress((void**)&pk,      g_k);
    cudaGetSymbolAddress((void**)&pv,      g_v);

    const int SMEM1 = NSTAGE * 2 * T_BYTES;   // TERMS=1: 73728
    const int SMEM2 = NSTAGE * 3 * T_BYTES;   // TERMS=2: 110592
    cudaFuncSetAttribute((const void*)tc_gemm<0,1>, cudaFuncAttributeMaxDynamicSharedMemorySize, SMEM1);
    cudaFuncSetAttribute((const void*)tc_gemm<1,2>, cudaFuncAttributeMaxDynamicSharedMemorySize, SMEM2);
    cudaFuncSetAttribute((const void*)tc_gemm<2,1>, cudaFuncAttributeMaxDynamicSharedMemorySize, SMEM1);
    cudaFuncSetAttribute((const void*)tc_gemm<3,1>, cudaFuncAttributeMaxDynamicSharedMemorySize, SMEM1);
    cudaFuncSetAttribute((const void*)tc_gemm<4,1>, cudaFuncAttributeMaxDynamicSharedMemorySize, SMEM1);

    // ---- input conversions ----
    extract_kernel<<<(ROWS * KPAD1 / 4 + 255) / 256, 256>>>(x);
    wconv_w1_kernel<<<dim3(KPAD1 / 32, HIDDEN / 32, NUM_SUBNETS), 256>>>(W1);

    W13 wa;
    for (int z = 0; z < 8; z++) {
        wa.src[z] = W2 + (size_t)z * HIDDEN * HIDDEN;
        wa.dhi[z] = W2T_hi + (size_t)z * HIDDEN * HIDDEN;
        wa.dlo[z] = W2T_lo + (size_t)z * HIDDEN * HIDDEN;
    }
    const float* srcs[5] = { Wq, Wk, Wv, Wo, Wp };
    __half* dhis[5] = { WqkvT_hi, WqkvT_hi + 512 * 512, WqkvT_hi + 1024 * 512, WoT_hi, WpT_hi };
    for (int z = 0; z < 5; z++) {
        wa.src[8 + z] = srcs[z];
        wa.dhi[8 + z] = dhis[z];
        wa.dlo[8 + z] = nullptr;            // single-term: no lo plane
    }
    wconv512_kernel<<<dim3(16, 16, 13), 256>>>(wa);

    dim3 g512(HIDDEN / BN, ROWS / BM);        // 8 x 32 = 256 CTAs
    dim3 gqkv(3 * HIDDEN / BN, ROWS / BM);    // 24 x 32 = 768 CTAs

    // GEMM1: h = relu(flat @ W1 + b1) -> fp16   (single-term weights)
    tc_gemm<0,1><<<g512, 256, SMEM1>>>(flat, KPAD1, W1T_hi, W1T_hi, KPAD1,
        (long)HIDDEN * KPAD1, KPAD1 / BK, b1, nullptr, h,
        nullptr, nullptr, nullptr, nullptr, nullptr, nullptr, nullptr);
    // GEMM2: xsub = h @ W2 + b2 (fp32, two-term weights - residual path accuracy)
    tc_gemm<1,2><<<g512, 256, SMEM2>>>(h, HIDDEN, W2T_hi, W2T_lo, HIDDEN,
        (long)HIDDEN * HIDDEN, HIDDEN / BK, b2, xsub, nullptr,
        nullptr, nullptr, nullptr, nullptr, nullptr, nullptr, nullptr);
    // LN -> xn fp16
    ln_kernel<<<ROWS, 256>>>(ln_g, ln_b);
    // QKV fused (single-term weights)
    tc_gemm<2,1><<<gqkv, 256, SMEM1>>>(xn, HIDDEN, WqkvT_hi, WqkvT_hi, HIDDEN,
        0L, HIDDEN / BK, nullptr, nullptr, nullptr,
        nullptr, pq, pk, pv, bq, bk, bv);
    // attention -> ctx fp16
    attn_kernel<<<BATCH, 256>>>();
    // O: t = ctx @ Wo + bo -> fp16 (single-term)
    tc_gemm<3,1><<<g512, 256, SMEM1>>>(ctx, HIDDEN, WoT_hi, WoT_hi, HIDDEN,
        0L, HIDDEN / BK, bo, nullptr, t,
        nullptr, nullptr, nullptr, nullptr, nullptr, nullptr, nullptr);
    // P: out = t @ Wp + bp + xsub (permuted to (b,s)) (single-term)
    tc_gemm<4,1><<<g512, 256, SMEM1>>>(t, HIDDEN, WpT_hi, WpT_hi, HIDDEN,
        0L, HIDDEN / BK, bp, out, nullptr,
        xsub, nullptr, nullptr, nullptr, nullptr, nullptr, nullptr);
}

// round 11
// speedup vs baseline: 1.7331x; 1.0350x over previous
#include <cuda_runtime.h>
#include <cuda_fp16.h>
#include <math.h>
#include <cstdint>

// ---------------- problem constants ----------------
#define NUM_SUBNETS 8
#define REGIONS     50
#define TOTAL_R     400
#define HIDDEN      512
#define HEADS       8
#define HEAD_DIM    64
#define BATCH       256
#define FLAT        2500
#define ROWS        (NUM_SUBNETS * BATCH)   // 2048
#define LN_EPS      1e-5f
#define KPAD1       2560                    // FLAT padded to multiple of 64

// GEMM tiling: A single fp16; W either single fp16 (TERMS=1) or split hi/lo (TERMS=2).
#define BM 64
#define BN 64
#define BK 64
#define ASTRIDE 144                         // bytes per 64-col fp16 row (128 + 16 pad)
#define T_BYTES (BM * ASTRIDE)              // 9216 per tile array

// merged conversion kernel block ranges
#define NB_E  (ROWS * KPAD1 / 1024)         // 5120 extract blocks (256 thr x 4 elems)
#define NB_W1 (NUM_SUBNETS * (KPAD1 / 32) * (HIDDEN / 32))  // 10240
#define NB_W5 (13 * 256)                    // 3328
#define NB_ALL (NB_E + NB_W1 + NB_W5)       // 18688

typedef unsigned long long u64;

// ---------------- scratch (device globals) ----------------
__device__ __half g_flat[ROWS * KPAD1];
__device__ __half g_W1T_hi[NUM_SUBNETS * HIDDEN * KPAD1];
__device__ __half g_W2T_hi[NUM_SUBNETS * HIDDEN * HIDDEN];
__device__ __half g_W2T_lo[NUM_SUBNETS * HIDDEN * HIDDEN];
__device__ __half g_WqkvT_hi[3 * HIDDEN * HIDDEN];
__device__ __half g_WoT_hi[HIDDEN * HIDDEN];
__device__ __half g_WpT_hi[HIDDEN * HIDDEN];

__device__ __half g_h  [ROWS * HIDDEN];
__device__ float  g_xsub[ROWS * HIDDEN];
__device__ __half g_xn [ROWS * HIDDEN];
__device__ __half g_q  [ROWS * HIDDEN];
__device__ __half g_k  [ROWS * HIDDEN];
__device__ __half g_v  [ROWS * HIDDEN];
__device__ __half g_ctx[ROWS * HIDDEN];
__device__ __half g_t  [ROWS * HIDDEN];

// ---------------- PTX helpers (sm_80-ratified only) ----------------
__device__ __forceinline__ uint32_t smem_u32(const void* p) {
    uint32_t a;
    asm("{ .reg .u64 t; cvta.to.shared.u64 t, %1; cvt.u32.u64 %0, t; }" : "=r"(a) : "l"(p));
    return a;
}
__device__ __forceinline__ void cpa16(uint32_t s, const void* g) {
    asm volatile("cp.async.cg.shared.global [%0], [%1], 16;" :: "r"(s), "l"(g));
}
__device__ __forceinline__ void cpa_commit() {
    asm volatile("cp.async.commit_group;" ::: "memory");
}
template<int N> __device__ __forceinline__ void cpa_wait() {
    asm volatile("cp.async.wait_group %0;" :: "n"(N) : "memory");
}
__device__ __forceinline__ void ldm4(uint32_t a, uint32_t* r) {
    asm volatile("ldmatrix.sync.aligned.m8n8.x4.shared.b16 {%0,%1,%2,%3}, [%4];"
        : "=r"(r[0]), "=r"(r[1]), "=r"(r[2]), "=r"(r[3]) : "r"(a));
}
__device__ __forceinline__ void mma16816(float* c, const uint32_t* a, uint32_t b0, uint32_t b1) {
    asm volatile("mma.sync.aligned.m16n8k16.row.col.f32.f16.f16.f32 "
        "{%0,%1,%2,%3},{%4,%5,%6,%7},{%8,%9},{%0,%1,%2,%3};"
        : "+f"(c[0]), "+f"(c[1]), "+f"(c[2]), "+f"(c[3])
        : "r"(a[0]), "r"(a[1]), "r"(a[2]), "r"(a[3]), "r"(b0), "r"(b1));
}

__device__ __forceinline__ void store_h2(__half* dst, size_t off, float v0, float v1) {
    *(__half2*)(dst + off) = __floats2half2_rn(v0, v1);
}

union H4 { uint2 u; __half2 p[2]; };

__device__ __forceinline__ void wsplit4(const float* v, H4& hv, H4& lv) {
    __half h0 = __float2half_rn(v[0]);
    __half h1 = __float2half_rn(v[1]);
    __half h2 = __float2half_rn(v[2]);
    __half h3 = __float2half_rn(v[3]);
    hv.p[0] = __halves2half2(h0, h1);
    hv.p[1] = __halves2half2(h2, h3);
    lv.p[0] = __halves2half2(__float2half_rn(v[0] - __half2float(h0)),
                             __float2half_rn(v[1] - __half2float(h1)));
    lv.p[1] = __halves2half2(__float2half_rn(v[2] - __half2float(h2)),
                             __float2half_rn(v[3] - __half2float(h3)));
}

// ---------------- merged conversion kernel ----------------
// block ranges: [0,NB_E) extract | [NB_E,NB_E+NB_W1) W1 transpose | rest: 13x 512x512 transpose
struct W13 {
    const float* src[13];
    __half* dhi[13];
    __half* dlo[13];    // nullptr -> single-term slice (no lo plane)
};

__global__ __launch_bounds__(256) void convert_all_kernel(
    const float* __restrict__ x, const float* __restrict__ W1, W13 wa)
{
    __shared__ float tile[32][33];
    const int tid = threadIdx.x;
    int id = blockIdx.x;

    if (id < NB_E) {
        // ---- extract diagonal blocks -> fp16 (4 elems/thread) ----
        int q = id * 256 + tid;
        int f0 = (q % (KPAD1 / 4)) * 4;
        int sb = q / (KPAD1 / 4);
        int b  = sb & (BATCH - 1);
        int s  = sb >> 8;
        const float* xb = x + (size_t)b * (TOTAL_R * TOTAL_R);
        float v[4];
        #pragma unroll
        for (int e = 0; e < 4; e++) {
            int f = f0 + e;
            float vv = 0.f;
            if (f < FLAT) {
                int i = f / REGIONS;
                int j = f - i * REGIONS;
                vv = xb[(s * REGIONS + i) * TOTAL_R + (s * REGIONS + j)];
            }
            v[e] = vv;
        }
        H4 hv;
        hv.p[0] = __floats2half2_rn(v[0], v[1]);
        hv.p[1] = __floats2half2_rn(v[2], v[3]);
        *(uint2*)(g_flat + (size_t)sb * KPAD1 + f0) = hv.u;
        return;
    }

    if (id < NB_E + NB_W1) {
        // ---- W1 transpose: [s][2500][512] -> [s][512][2560] single fp16 ----
        int id2 = id - NB_E;
        int z   = id2 / 1280;
        int rem = id2 % 1280;
        int k0  = (rem % 80) * 32;
        int n0  = (rem / 80) * 32;
        const float* sp = W1 + (size_t)z * FLAT * HIDDEN;
        // float4 global loads: 256 threads x 1 float4 = 32 rows x 8 float4
        {
            int row = tid >> 3, c4 = (tid & 7) * 4;
            int k = k0 + row;
            float4 vv = make_float4(0.f, 0.f, 0.f, 0.f);
            if (k < FLAT) vv = *(const float4*)(sp + (size_t)k * HIDDEN + n0 + c4);
            tile[row][c4]     = vv.x;
            tile[row][c4 + 1] = vv.y;
            tile[row][c4 + 2] = vv.z;
            tile[row][c4 + 3] = vv.w;
        }
        __syncthreads();
        int n = tid >> 3, kq = (tid & 7) * 4;
        H4 hv;
        hv.p[0] = __floats2half2_rn(tile[kq][n],     tile[kq + 1][n]);
        hv.p[1] = __floats2half2_rn(tile[kq + 2][n], tile[kq + 3][n]);
        size_t dbase = (size_t)z * HIDDEN * KPAD1;
        *(uint2*)(g_W1T_hi + dbase + (size_t)(n0 + n) * KPAD1 + k0 + kq) = hv.u;
        return;
    }

    // ---- 512x512 transpose (+ optional lo split) ----
    {
        int id3 = id - NB_E - NB_W1;
        int z   = id3 >> 8;
        int rem = id3 & 255;
        int k0  = (rem & 15) * 32;
        int n0  = (rem >> 4) * 32;
        const float* sp = wa.src[z];
        __half* dhi = wa.dhi[z];
        __half* dlo = wa.dlo[z];
        {
            int row = tid >> 3, c4 = (tid & 7) * 4;
            float4 vv = *(const float4*)(sp + (size_t)(k0 + row) * HIDDEN + n0 + c4);
            tile[row][c4]     = vv.x;
            tile[row][c4 + 1] = vv.y;
            tile[row][c4 + 2] = vv.z;
            tile[row][c4 + 3] = vv.w;
        }
        __syncthreads();
        int n = tid >> 3, kq = (tid & 7) * 4;
        float v[4];
        #pragma unroll
        for (int i = 0; i < 4; i++) v[i] = tile[kq + i][n];
        size_t off = (size_t)(n0 + n) * HIDDEN + k0 + kq;
        if (dlo) {
            H4 hv, lv; wsplit4(v, hv, lv);
            *(uint2*)(dhi + off) = hv.u;
            *(uint2*)(dlo + off) = lv.u;
        } else {
            H4 hv;
            hv.p[0] = __floats2half2_rn(v[0], v[1]);
            hv.p[1] = __floats2half2_rn(v[2], v[3]);
            *(uint2*)(dhi + off) = hv.u;
        }
    }
}

// ---------------- mma.sync GEMM: C[2048][N] = A[2048][K] * W^T + epilogue ----------------
// TERMS=2: C = A*Wh + A*Wl; TERMS=1: C = A*Wh. fp32 accum. BM=BN=64, BK=64,
// NST-stage cp.async pipeline (NST=3 when OCC>=3 else 4), 8 warps
// (wm 2)x(wn 2)x(wk 2), warp tile 32x32, K split across wk + SMEM reduce.
// EP: 0 relu->fp16 | 1 f32 | 2 qkv split fp16 | 3 fp16 | 4 resid+permute f32
template<int EP, int TERMS, int OCC>
__global__ __launch_bounds__(256, OCC) void tc_gemm(
    const __half* __restrict__ A, int sA,
    const __half* __restrict__ Bhi, const __half* __restrict__ Blo, int sB,
    long bSub, int Ksteps,
    const float* __restrict__ bias,
    float* __restrict__ o32,
    __half* __restrict__ oH,
    const float* __restrict__ resid,
    __half* __restrict__ oq, __half* __restrict__ okk, __half* __restrict__ ov,
    const float* __restrict__ bq, const float* __restrict__ bk, const float* __restrict__ bv)
{
    constexpr int NST = (OCC >= 3) ? 3 : 4;
    constexpr uint32_t STG = (TERMS + 1) * T_BYTES;   // A + TERMS B tiles
    extern __shared__ __align__(128) char smem[];
    const uint32_t sbase = smem_u32(smem);
    const int tid = threadIdx.x;
    const int mBase = blockIdx.y * BM;
    const int nBase = blockIdx.x * BN;
    const int sIdx = blockIdx.y >> 2;        // 4 M-tiles (256 rows) per subnet

    const __half* aP = A + (size_t)mBase * sA;
    size_t boff = (bSub > 0 ? (size_t)sIdx * (size_t)bSub : 0) + (size_t)nBase * sB;
    const __half* bH = Bhi + boff;
    const __half* bL = Blo + boff;
    const float* biasP = bias ? (bias + (bSub > 0 ? sIdx * HIDDEN : 0)) : bias;

    // ---- async-copy one K-chunk; ALWAYS commits exactly one group ----
    auto issue = [&](int chunk) {
        if (chunk < Ksteps) {
            const uint32_t st = sbase + (chunk % NST) * STG;
            const int k0 = chunk * BK;
            #pragma unroll
            for (int i = 0; i < 2; i++) {
                int idx = tid + i * 256;
                int row = idx >> 3, c = idx & 7;
                cpa16(st + row * ASTRIDE + c * 16, aP + (size_t)row * sA + k0 + c * 8);
            }
            #pragma unroll
            for (int i = 0; i < 2; i++) {
                int idx = tid + i * 256;
                int row = idx >> 3, c = idx & 7;
                uint32_t so = st + T_BYTES + row * ASTRIDE + c * 16;
                cpa16(so, bH + (size_t)row * sB + k0 + c * 8);
                if (TERMS == 2)
                    cpa16(so + T_BYTES, bL + (size_t)row * sB + k0 + c * 8);
            }
        }
        cpa_commit();
    };

    #pragma unroll
    for (int i = 0; i < NST - 1; i++) issue(i);

    const int wid = tid >> 5, lane = tid & 31;
    const int wk = wid >> 2;                 // 0/1 : handles kk = 2*wk + {0,1}
    const int wm = (wid >> 1) & 1;           // 32-row half
    const int wn = wid & 1;                  // 32-col half
    const uint32_t lrow = lane & 15;
    const uint32_t lcol = (lane >> 4) * 16;

    float acc[2][4][4];                      // [m16 tile][n8 tile][frag]
    #pragma unroll
    for (int i = 0; i < 2; i++)
        #pragma unroll
        for (int j = 0; j < 4; j++)
            #pragma unroll
            for (int t = 0; t < 4; t++) acc[i][j][t] = 0.f;

    for (int s = 0; s < Ksteps; ++s) {
        cpa_wait<NST - 2>();           // stage s landed
        __syncthreads();               // all warps done with freed buffer
        issue(s + NST - 1);            // refill it, overlaps compute
        const uint32_t st = sbase + (s % NST) * STG;
        #pragma unroll
        for (int j = 0; j < 2; ++j) {
            const int kk = wk * 2 + j;
            uint32_t aF[2][4], bHf[2][4], bLf[2][4];
            #pragma unroll
            for (int am = 0; am < 2; am++) {
                uint32_t ad = st + (wm * 32 + am * 16 + lrow) * ASTRIDE + kk * 32 + lcol;
                ldm4(ad, aF[am]);
            }
            #pragma unroll
            for (int bt = 0; bt < 2; bt++) {
                uint32_t bd = st + T_BYTES + (wn * 32 + bt * 16 + lrow) * ASTRIDE + kk * 32 + lcol;
                ldm4(bd, bHf[bt]);
                if (TERMS == 2) ldm4(bd + T_BYTES, bLf[bt]);
            }
            // term-major: acc reuse distance 8
            #pragma unroll
            for (int am = 0; am < 2; am++)
                #pragma unroll
                for (int bt = 0; bt < 2; bt++) {
                    mma16816(acc[am][2*bt],   aF[am], bHf[bt][0], bHf[bt][2]);
                    mma16816(acc[am][2*bt+1], aF[am], bHf[bt][1], bHf[bt][3]);
                }
            if (TERMS == 2) {
                #pragma unroll
                for (int am = 0; am < 2; am++)
                    #pragma unroll
                    for (int bt = 0; bt < 2; bt++) {
                        mma16816(acc[am][2*bt],   aF[am], bLf[bt][0], bLf[bt][2]);
                        mma16816(acc[am][2*bt+1], aF[am], bLf[bt][1], bLf[bt][3]);
                    }
            }
        }
    }

    // ---- reduce wk=1 partial sums into wk=0 via SMEM (stages are dead now) ----
    __syncthreads();
    float* red = (float*)smem;               // 4 regions of [32][34] floats
    float* rbase = red + (wm * 2 + wn) * (32 * 34);
    if (wk == 1) {
        #pragma unroll
        for (int am = 0; am < 2; am++)
            #pragma unroll
            for (int an = 0; an < 4; an++)
                #pragma unroll
                for (int t = 0; t < 4; t++) {
                    int row = am * 16 + (lane >> 2) + (t >> 1) * 8;
                    int col = an * 8 + (lane & 3) * 2 + (t & 1);
                    rbase[row * 34 + col] = acc[am][an][t];
                }
    }
    __syncthreads();
    if (wk == 1) return;
    #pragma unroll
    for (int am = 0; am < 2; am++)
        #pragma unroll
        for (int an = 0; an < 4; an++)
            #pragma unroll
            for (int t = 0; t < 4; t++) {
                int row = am * 16 + (lane >> 2) + (t >> 1) * 8;
                int col = an * 8 + (lane & 3) * 2 + (t & 1);
                acc[am][an][t] += rbase[row * 34 + col];
            }

    // ---- epilogue (wk=0 warps only): registers -> global ----
    #pragma unroll
    for (int am = 0; am < 2; am++) {
        #pragma unroll
        for (int an = 0; an < 4; an++) {
            int m0 = mBase + wm * 32 + am * 16 + (lane >> 2);
            int g  = nBase + wn * 32 + an * 8 + (lane & 3) * 2;
            #pragma unroll
            for (int half = 0; half < 2; half++) {
                int m = m0 + half * 8;
                float v0 = acc[am][an][half * 2];
                float v1 = acc[am][an][half * 2 + 1];
                if (EP == 0) {                          // relu -> fp16
                    v0 = fmaxf(v0 + biasP[g], 0.f);
                    v1 = fmaxf(v1 + biasP[g + 1], 0.f);
                    store_h2(oH, (size_t)m * HIDDEN + g, v0, v1);
                } else if (EP == 1) {                   // xsub fp32
                    v0 += biasP[g]; v1 += biasP[g + 1];
                    *(float2*)(o32 + (size_t)m * HIDDEN + g) = make_float2(v0, v1);
                } else if (EP == 2) {                   // qkv split fp16
                    int which = g >> 9, lc = g & 511;
                    const float* bb = (which == 0) ? bq : (which == 1) ? bk : bv;
                    __half* dst = (which == 0) ? oq : (which == 1) ? okk : ov;
                    v0 += bb[lc]; v1 += bb[lc + 1];
                    store_h2(dst, (size_t)m * HIDDEN + lc, v0, v1);
                } else if (EP == 3) {                   // fp16 out (t)
                    v0 += biasP[g]; v1 += biasP[g + 1];
                    store_h2(oH, (size_t)m * HIDDEN + g, v0, v1);
                } else {                                // out = . + bp + xsub, (b,s) order
                    v0 += biasP[g] + resid[(size_t)m * HIDDEN + g];
                    v1 += biasP[g + 1] + resid[(size_t)m * HIDDEN + g + 1];
                    int bb2 = m & (BATCH - 1), ss = m >> 8;
                    *(float2*)(o32 + ((size_t)((bb2 << 3) + ss)) * HIDDEN + g) = make_float2(v0, v1);
                }
            }
        }
    }
}

// ---------------- LayerNorm: xsub fp32 -> xn fp16 ----------------
__global__ __launch_bounds__(256) void ln_kernel(const float* __restrict__ lng,
                                                 const float* __restrict__ lnb)
{
    int r = blockIdx.x, t = threadIdx.x;
    const float* xs = g_xsub + (size_t)r * HIDDEN;
    float v0 = xs[t], v1 = xs[t + 256];
    float s = v0 + v1, q = v0 * v0 + v1 * v1;
    #pragma unroll
    for (int o = 16; o > 0; o >>= 1) {
        s += __shfl_xor_sync(0xFFFFFFFFu, s, o);
        q += __shfl_xor_sync(0xFFFFFFFFu, q, o);
    }
    __shared__ float ss[8], sq[8];
    int w = t >> 5, l = t & 31;
    if (l == 0) { ss[w] = s; sq[w] = q; }
    __syncthreads();
    if (w == 0) {
        float a = (l < 8) ? ss[l] : 0.f;
        float c = (l < 8) ? sq[l] : 0.f;
        #pragma unroll
        for (int o = 4; o > 0; o >>= 1) {
            a += __shfl_xor_sync(0xFFFFFFFFu, a, o);
            c += __shfl_xor_sync(0xFFFFFFFFu, c, o);
        }
        if (l == 0) { ss[0] = a; sq[0] = c; }
    }
    __syncthreads();
    float mean = ss[0] * (1.f / HIDDEN);
    float var  = sq[0] * (1.f / HIDDEN) - mean * mean;
    float inv  = rsqrtf(var + LN_EPS);
    float o0 = (v0 - mean) * inv * lng[t] + lnb[t];
    float o1 = (v1 - mean) * inv * lng[t + 256] + lnb[t + 256];
    size_t base = (size_t)r * HIDDEN;
    g_xn[base + t]       = __float2half_rn(o0);
    g_xn[base + t + 256] = __float2half_rn(o1);
}

// ---------------- attention: q,k,v fp16 -> ctx fp16 ----------------
__global__ __launch_bounds__(256) void attn_kernel()
{
    __shared__ float q_s[NUM_SUBNETS][520];
    __shared__ float k_s[NUM_SUBNETS][520];
    __shared__ float sc[HEADS][NUM_SUBNETS][NUM_SUBNETS];

    int b = blockIdx.x;
    int tid = threadIdx.x;

    for (int i = tid; i < NUM_SUBNETS * HIDDEN; i += 256) {
        int m = i >> 9, c = i & 511;
        size_t gi = ((size_t)(m * BATCH + b)) * HIDDEN + c;
        q_s[m][c] = __half2float(g_q[gi]);
        k_s[m][c] = __half2float(g_k[gi]);
    }
    __syncthreads();

    int h = tid >> 5, l = tid & 31;

    #pragma unroll
    for (int pp = 0; pp < 2; pp++) {
        int p = l + pp * 32;
        int m = p >> 3, n = p & 7;
        const float* qp = &q_s[m][h * HEAD_DIM];
        const float* kp = &k_s[n][h * HEAD_DIM];
        float sv = 0.f;
        #pragma unroll
        for (int d = 0; d < HEAD_DIM; d++) sv += qp[d] * kp[d];
        sv *= 0.125f;
        sc[h][m][n] = (m == n) ? 0.f : sv;
    }
    __syncwarp();

    if (l < NUM_SUBNETS) {
        float mx = -1e30f;
        #pragma unroll
        for (int n = 0; n < 8; n++) mx = fmaxf(mx, sc[h][l][n]);
        float e[8], sum = 0.f;
        #pragma unroll
        for (int n = 0; n < 8; n++) { e[n] = expf(sc[h][l][n] - mx); sum += e[n]; }
        float inv = 1.f / sum;
        #pragma unroll
        for (int n = 0; n < 8; n++) sc[h][l][n] = e[n] * inv;
    }
    __syncwarp();

    #pragma unroll
    for (int dd = 0; dd < 2; dd++) {
        int d = l + dd * 32;
        float vv[8];
        #pragma unroll
        for (int n = 0; n < 8; n++)
            vv[n] = __half2float(g_v[((size_t)(n * BATCH + b)) * HIDDEN + h * HEAD_DIM + d]);
        #pragma unroll
        for (int m = 0; m < 8; m++) {
            float cv = 0.f;
            #pragma unroll
            for (int n = 0; n < 8; n++) cv += sc[h][m][n] * vv[n];
            g_ctx[((size_t)(m * BATCH + b)) * HIDDEN + h * HEAD_DIM + d] = __float2half_rn(cv);
        }
    }
}

// ---------------- launch ----------------
extern "C" void kernel_launch(void* const* d_in, const int* in_sizes, int n_in,
                              void* d_out, int out_size)
{
    (void)in_sizes; (void)n_in; (void)out_size;
    const float* x    = (const float*)d_in[0];
    const float* W1   = (const float*)d_in[2];
    const float* b1   = (const float*)d_in[3];
    const float* W2   = (const float*)d_in[4];
    const float* b2   = (const float*)d_in[5];
    const float* ln_g = (const float*)d_in[6];
    const float* ln_b = (const float*)d_in[7];
    const float* Wq   = (const float*)d_in[8];
    const float* bq   = (const float*)d_in[9];
    const float* Wk   = (const float*)d_in[10];
    const float* bk   = (const float*)d_in[11];
    const float* Wv   = (const float*)d_in[12];
    const float* bv   = (const float*)d_in[13];
    const float* Wo   = (const float*)d_in[14];
    const float* bo   = (const float*)d_in[15];
    const float* Wp   = (const float*)d_in[16];
    const float* bp   = (const float*)d_in[17];
    float* out = (float*)d_out;

    __half *flat, *W1T_hi, *W2T_hi, *W2T_lo, *WqkvT_hi, *WoT_hi, *WpT_hi;
    __half *h, *xn, *ctx, *t, *pq, *pk, *pv;
    float *xsub;
    cudaGetSymbolAddress((void**)&flat,    g_flat);
    cudaGetSymbolAddress((void**)&W1T_hi,  g_W1T_hi);
    cudaGetSymbolAddress((void**)&W2T_hi,  g_W2T_hi);
    cudaGetSymbolAddress((void**)&W2T_lo,  g_W2T_lo);
    cudaGetSymbolAddress((void**)&WqkvT_hi, g_WqkvT_hi);
    cudaGetSymbolAddress((void**)&WoT_hi,  g_WoT_hi);
    cudaGetSymbolAddress((void**)&WpT_hi,  g_WpT_hi);
    cudaGetSymbolAddress((void**)&h,       g_h);
    cudaGetSymbolAddress((void**)&xn,      g_xn);
    cudaGetSymbolAddress((void**)&ctx,     g_ctx);
    cudaGetSymbolAddress((void**)&t,       g_t);
    cudaGetSymbolAddress((void**)&xsub,    g_xsub);
    cudaGetSymbolAddress((void**)&pq,      g_q);
    cudaGetSymbolAddress((void**)&pk,      g_k);
    cudaGetSymbolAddress((void**)&pv,      g_v);

    const int SMEM1  = 4 * 2 * T_BYTES;   // TERMS=1, OCC=2: 73728
    const int SMEM2  = 4 * 3 * T_BYTES;   // TERMS=2, OCC=2: 110592
    const int SMEMQ  = 3 * 2 * T_BYTES;   // TERMS=1, OCC=3: 55296
    cudaFuncSetAttribute((const void*)tc_gemm<0,1,2>, cudaFuncAttributeMaxDynamicSharedMemorySize, SMEM1);
    cudaFuncSetAttribute((const void*)tc_gemm<1,2,2>, cudaFuncAttributeMaxDynamicSharedMemorySize, SMEM2);
    cudaFuncSetAttribute((const void*)tc_gemm<2,1,3>, cudaFuncAttributeMaxDynamicSharedMemorySize, SMEMQ);
    cudaFuncSetAttribute((const void*)tc_gemm<3,1,2>, cudaFuncAttributeMaxDynamicSharedMemorySize, SMEM1);
    cudaFuncSetAttribute((const void*)tc_gemm<4,1,2>, cudaFuncAttributeMaxDynamicSharedMemorySize, SMEM1);

    // ---- all input conversions in ONE launch ----
    W13 wa;
    for (int z = 0; z < 8; z++) {
        wa.src[z] = W2 + (size_t)z * HIDDEN * HIDDEN;
        wa.dhi[z] = W2T_hi + (size_t)z * HIDDEN * HIDDEN;
        wa.dlo[z] = W2T_lo + (size_t)z * HIDDEN * HIDDEN;
    }
    const float* srcs[5] = { Wq, Wk, Wv, Wo, Wp };
    __half* dhis[5] = { WqkvT_hi, WqkvT_hi + 512 * 512, WqkvT_hi + 1024 * 512, WoT_hi, WpT_hi };
    for (int z = 0; z < 5; z++) {
        wa.src[8 + z] = srcs[z];
        wa.dhi[8 + z] = dhis[z];
        wa.dlo[8 + z] = nullptr;
    }
    convert_all_kernel<<<NB_ALL, 256>>>(x, W1, wa);

    dim3 g512(HIDDEN / BN, ROWS / BM);        // 8 x 32 = 256 CTAs
    dim3 gqkv(3 * HIDDEN / BN, ROWS / BM);    // 24 x 32 = 768 CTAs

    // GEMM1: h = relu(flat @ W1 + b1) -> fp16   (single-term weights)
    tc_gemm<0,1,2><<<g512, 256, SMEM1>>>(flat, KPAD1, W1T_hi, W1T_hi, KPAD1,
        (long)HIDDEN * KPAD1, KPAD1 / BK, b1, nullptr, h,
        nullptr, nullptr, nullptr, nullptr, nullptr, nullptr, nullptr);
    // GEMM2: xsub = h @ W2 + b2 (fp32, two-term weights - residual path accuracy)
    tc_gemm<1,2,2><<<g512, 256, SMEM2>>>(h, HIDDEN, W2T_hi, W2T_lo, HIDDEN,
        (long)HIDDEN * HIDDEN, HIDDEN / BK, b2, xsub, nullptr,
        nullptr, nullptr, nullptr, nullptr, nullptr, nullptr, nullptr);
    // LN -> xn fp16
    ln_kernel<<<ROWS, 256>>>(ln_g, ln_b);
    // QKV fused (single-term weights, fp16 outputs, 3 CTAs/SM)
    tc_gemm<2,1,3><<<gqkv, 256, SMEMQ>>>(xn, HIDDEN, WqkvT_hi, WqkvT_hi, HIDDEN,
        0L, HIDDEN / BK, nullptr, nullptr, nullptr,
        nullptr, pq, pk, pv, bq, bk, bv);
    // attention -> ctx fp16
    attn_kernel<<<BATCH, 256>>>();
    // O: t = ctx @ Wo + bo -> fp16 (single-term)
    tc_gemm<3,1,2><<<g512, 256, SMEM1>>>(ctx, HIDDEN, WoT_hi, WoT_hi, HIDDEN,
        0L, HIDDEN / BK, bo, nullptr, t,
        nullptr, nullptr, nullptr, nullptr, nullptr, nullptr, nullptr);
    // P: out = t @ Wp + bp + xsub (permuted to (b,s)) (single-term)
    tc_gemm<4,1,2><<<g512, 256, SMEM1>>>(t, HIDDEN, WpT_hi, WpT_hi, HIDDEN,
        0L, HIDDEN / BK, bp, out, nullptr,
        xsub, nullptr, nullptr, nullptr, nullptr, nullptr, nullptr);
}

// round 12
// speedup vs baseline: 1.7900x; 1.0328x over previous
#include <cuda_runtime.h>
#include <cuda_fp16.h>
#include <math.h>
#include <cstdint>

// ---------------- problem constants ----------------
#define NUM_SUBNETS 8
#define REGIONS     50
#define TOTAL_R     400
#define HIDDEN      512
#define HEADS       8
#define HEAD_DIM    64
#define BATCH       256
#define FLAT        2500
#define ROWS        (NUM_SUBNETS * BATCH)   // 2048
#define LN_EPS      1e-5f
#define KPAD1       2560                    // FLAT padded to multiple of 64

// GEMM tiling: A single fp16, W single fp16 (all GEMMs TERMS=1 now).
#define BM 64
#define BN 64
#define BK 64
#define ASTRIDE 144                         // bytes per 64-col fp16 row (128 + 16 pad)
#define T_BYTES (BM * ASTRIDE)              // 9216 per tile array

// merged conversion kernel block ranges
#define NB_E  (ROWS * KPAD1 / 1024)         // 5120 extract blocks (256 thr x 4 elems)
#define NB_W1 (NUM_SUBNETS * (KPAD1 / 32) * (HIDDEN / 32))  // 10240
#define NB_W5 (13 * 256)                    // 3328
#define NB_ALL (NB_E + NB_W1 + NB_W5)       // 18688

typedef unsigned long long u64;

// ---------------- scratch (device globals) ----------------
__device__ __half g_flat[ROWS * KPAD1];
__device__ __half g_W1T_hi[NUM_SUBNETS * HIDDEN * KPAD1];
__device__ __half g_W2T_hi[NUM_SUBNETS * HIDDEN * HIDDEN];
__device__ __half g_WqkvT_hi[3 * HIDDEN * HIDDEN];
__device__ __half g_WoT_hi[HIDDEN * HIDDEN];
__device__ __half g_WpT_hi[HIDDEN * HIDDEN];

__device__ __half g_h  [ROWS * HIDDEN];
__device__ float  g_xsub[ROWS * HIDDEN];
__device__ __half g_xn [ROWS * HIDDEN];
__device__ __half g_q  [ROWS * HIDDEN];
__device__ __half g_k  [ROWS * HIDDEN];
__device__ __half g_v  [ROWS * HIDDEN];
__device__ __half g_ctx[ROWS * HIDDEN];
__device__ __half g_t  [ROWS * HIDDEN];

// ---------------- PTX helpers (sm_80-ratified only) ----------------
__device__ __forceinline__ uint32_t smem_u32(const void* p) {
    uint32_t a;
    asm("{ .reg .u64 t; cvta.to.shared.u64 t, %1; cvt.u32.u64 %0, t; }" : "=r"(a) : "l"(p));
    return a;
}
__device__ __forceinline__ void cpa16(uint32_t s, const void* g) {
    asm volatile("cp.async.cg.shared.global [%0], [%1], 16;" :: "r"(s), "l"(g));
}
__device__ __forceinline__ void cpa_commit() {
    asm volatile("cp.async.commit_group;" ::: "memory");
}
template<int N> __device__ __forceinline__ void cpa_wait() {
    asm volatile("cp.async.wait_group %0;" :: "n"(N) : "memory");
}
__device__ __forceinline__ void ldm4(uint32_t a, uint32_t* r) {
    asm volatile("ldmatrix.sync.aligned.m8n8.x4.shared.b16 {%0,%1,%2,%3}, [%4];"
        : "=r"(r[0]), "=r"(r[1]), "=r"(r[2]), "=r"(r[3]) : "r"(a));
}
__device__ __forceinline__ void mma16816(float* c, const uint32_t* a, uint32_t b0, uint32_t b1) {
    asm volatile("mma.sync.aligned.m16n8k16.row.col.f32.f16.f16.f32 "
        "{%0,%1,%2,%3},{%4,%5,%6,%7},{%8,%9},{%0,%1,%2,%3};"
        : "+f"(c[0]), "+f"(c[1]), "+f"(c[2]), "+f"(c[3])
        : "r"(a[0]), "r"(a[1]), "r"(a[2]), "r"(a[3]), "r"(b0), "r"(b1));
}

__device__ __forceinline__ void store_h2(__half* dst, size_t off, float v0, float v1) {
    *(__half2*)(dst + off) = __floats2half2_rn(v0, v1);
}

union H4 { uint2 u; __half2 p[2]; };

// ---------------- merged conversion kernel ----------------
// block ranges: [0,NB_E) extract | [NB_E,NB_E+NB_W1) W1 transpose | rest: 13x 512x512 transpose
struct W13 {
    const float* src[13];
    __half* dhi[13];
};

__global__ __launch_bounds__(256) void convert_all_kernel(
    const float* __restrict__ x, const float* __restrict__ W1, W13 wa)
{
    __shared__ float tile[32][33];
    const int tid = threadIdx.x;
    int id = blockIdx.x;

    if (id < NB_E) {
        // ---- extract diagonal blocks -> fp16 (4 elems/thread) ----
        int q = id * 256 + tid;
        int f0 = (q % (KPAD1 / 4)) * 4;
        int sb = q / (KPAD1 / 4);
        int b  = sb & (BATCH - 1);
        int s  = sb >> 8;
        const float* xb = x + (size_t)b * (TOTAL_R * TOTAL_R);
        float v[4];
        #pragma unroll
        for (int e = 0; e < 4; e++) {
            int f = f0 + e;
            float vv = 0.f;
            if (f < FLAT) {
                int i = f / REGIONS;
                int j = f - i * REGIONS;
                vv = xb[(s * REGIONS + i) * TOTAL_R + (s * REGIONS + j)];
            }
            v[e] = vv;
        }
        H4 hv;
        hv.p[0] = __floats2half2_rn(v[0], v[1]);
        hv.p[1] = __floats2half2_rn(v[2], v[3]);
        *(uint2*)(g_flat + (size_t)sb * KPAD1 + f0) = hv.u;
        return;
    }

    if (id < NB_E + NB_W1) {
        // ---- W1 transpose: [s][2500][512] -> [s][512][2560] single fp16 ----
        int id2 = id - NB_E;
        int z   = id2 / 1280;
        int rem = id2 % 1280;
        int k0  = (rem % 80) * 32;
        int n0  = (rem / 80) * 32;
        const float* sp = W1 + (size_t)z * FLAT * HIDDEN;
        {
            int row = tid >> 3, c4 = (tid & 7) * 4;
            int k = k0 + row;
            float4 vv = make_float4(0.f, 0.f, 0.f, 0.f);
            if (k < FLAT) vv = *(const float4*)(sp + (size_t)k * HIDDEN + n0 + c4);
            tile[row][c4]     = vv.x;
            tile[row][c4 + 1] = vv.y;
            tile[row][c4 + 2] = vv.z;
            tile[row][c4 + 3] = vv.w;
        }
        __syncthreads();
        int n = tid >> 3, kq = (tid & 7) * 4;
        H4 hv;
        hv.p[0] = __floats2half2_rn(tile[kq][n],     tile[kq + 1][n]);
        hv.p[1] = __floats2half2_rn(tile[kq + 2][n], tile[kq + 3][n]);
        size_t dbase = (size_t)z * HIDDEN * KPAD1;
        *(uint2*)(g_W1T_hi + dbase + (size_t)(n0 + n) * KPAD1 + k0 + kq) = hv.u;
        return;
    }

    // ---- 512x512 transpose, single fp16 ----
    {
        int id3 = id - NB_E - NB_W1;
        int z   = id3 >> 8;
        int rem = id3 & 255;
        int k0  = (rem & 15) * 32;
        int n0  = (rem >> 4) * 32;
        const float* sp = wa.src[z];
        __half* dhi = wa.dhi[z];
        {
            int row = tid >> 3, c4 = (tid & 7) * 4;
            float4 vv = *(const float4*)(sp + (size_t)(k0 + row) * HIDDEN + n0 + c4);
            tile[row][c4]     = vv.x;
            tile[row][c4 + 1] = vv.y;
            tile[row][c4 + 2] = vv.z;
            tile[row][c4 + 3] = vv.w;
        }
        __syncthreads();
        int n = tid >> 3, kq = (tid & 7) * 4;
        H4 hv;
        hv.p[0] = __floats2half2_rn(tile[kq][n],     tile[kq + 1][n]);
        hv.p[1] = __floats2half2_rn(tile[kq + 2][n], tile[kq + 3][n]);
        *(uint2*)(dhi + (size_t)(n0 + n) * HIDDEN + k0 + kq) = hv.u;
    }
}

// ---------------- mma.sync GEMM: C[2048][N] = A[2048][K] * W^T + epilogue ----------------
// C = A*W (both single fp16), fp32 accum. BM=BN=64, BK=64, NST-stage cp.async
// pipeline, 8 warps (wm 2)x(wn 2)x(wk 2), warp tile 32x32, K split across wk
// + SMEM reduce. MMAs term-major.
// EP: 0 relu->fp16 | 1 f32 | 2 qkv split fp16 | 3 fp16 | 4 resid+permute f32
template<int EP, int OCC>
__global__ __launch_bounds__(256, OCC) void tc_gemm(
    const __half* __restrict__ A, int sA,
    const __half* __restrict__ Bhi, int sB,
    long bSub, int Ksteps,
    const float* __restrict__ bias,
    float* __restrict__ o32,
    __half* __restrict__ oH,
    const float* __restrict__ resid,
    __half* __restrict__ oq, __half* __restrict__ okk, __half* __restrict__ ov,
    const float* __restrict__ bq, const float* __restrict__ bk, const float* __restrict__ bv)
{
    constexpr int NST = (OCC >= 3) ? 3 : 4;
    constexpr uint32_t STG = 2 * T_BYTES;   // A + B
    extern __shared__ __align__(128) char smem[];
    const uint32_t sbase = smem_u32(smem);
    const int tid = threadIdx.x;
    const int mBase = blockIdx.y * BM;
    const int nBase = blockIdx.x * BN;
    const int sIdx = blockIdx.y >> 2;        // 4 M-tiles (256 rows) per subnet

    const __half* aP = A + (size_t)mBase * sA;
    size_t boff = (bSub > 0 ? (size_t)sIdx * (size_t)bSub : 0) + (size_t)nBase * sB;
    const __half* bH = Bhi + boff;
    const float* biasP = bias ? (bias + (bSub > 0 ? sIdx * HIDDEN : 0)) : bias;

    // ---- async-copy one K-chunk; ALWAYS commits exactly one group ----
    auto issue = [&](int chunk) {
        if (chunk < Ksteps) {
            const uint32_t st = sbase + (chunk % NST) * STG;
            const int k0 = chunk * BK;
            #pragma unroll
            for (int i = 0; i < 2; i++) {
                int idx = tid + i * 256;
                int row = idx >> 3, c = idx & 7;
                cpa16(st + row * ASTRIDE + c * 16, aP + (size_t)row * sA + k0 + c * 8);
                cpa16(st + T_BYTES + row * ASTRIDE + c * 16, bH + (size_t)row * sB + k0 + c * 8);
            }
        }
        cpa_commit();
    };

    #pragma unroll
    for (int i = 0; i < NST - 1; i++) issue(i);

    const int wid = tid >> 5, lane = tid & 31;
    const int wk = wid >> 2;                 // 0/1 : handles kk = 2*wk + {0,1}
    const int wm = (wid >> 1) & 1;           // 32-row half
    const int wn = wid & 1;                  // 32-col half
    const uint32_t lrow = lane & 15;
    const uint32_t lcol = (lane >> 4) * 16;

    float acc[2][4][4];                      // [m16 tile][n8 tile][frag]
    #pragma unroll
    for (int i = 0; i < 2; i++)
        #pragma unroll
        for (int j = 0; j < 4; j++)
            #pragma unroll
            for (int t = 0; t < 4; t++) acc[i][j][t] = 0.f;

    for (int s = 0; s < Ksteps; ++s) {
        cpa_wait<NST - 2>();           // stage s landed
        __syncthreads();               // all warps done with freed buffer
        issue(s + NST - 1);            // refill it, overlaps compute
        const uint32_t st = sbase + (s % NST) * STG;
        #pragma unroll
        for (int j = 0; j < 2; ++j) {
            const int kk = wk * 2 + j;
            uint32_t aF[2][4], bF[2][4];
            #pragma unroll
            for (int am = 0; am < 2; am++) {
                uint32_t ad = st + (wm * 32 + am * 16 + lrow) * ASTRIDE + kk * 32 + lcol;
                ldm4(ad, aF[am]);
            }
            #pragma unroll
            for (int bt = 0; bt < 2; bt++) {
                uint32_t bd = st + T_BYTES + (wn * 32 + bt * 16 + lrow) * ASTRIDE + kk * 32 + lcol;
                ldm4(bd, bF[bt]);
            }
            #pragma unroll
            for (int am = 0; am < 2; am++)
                #pragma unroll
                for (int bt = 0; bt < 2; bt++) {
                    mma16816(acc[am][2*bt],   aF[am], bF[bt][0], bF[bt][2]);
                    mma16816(acc[am][2*bt+1], aF[am], bF[bt][1], bF[bt][3]);
                }
        }
    }

    // ---- reduce wk=1 partial sums into wk=0 via SMEM (stages are dead now) ----
    __syncthreads();
    float* red = (float*)smem;               // 4 regions of [32][34] floats
    float* rbase = red + (wm * 2 + wn) * (32 * 34);
    if (wk == 1) {
        #pragma unroll
        for (int am = 0; am < 2; am++)
            #pragma unroll
            for (int an = 0; an < 4; an++)
                #pragma unroll
                for (int t = 0; t < 4; t++) {
                    int row = am * 16 + (lane >> 2) + (t >> 1) * 8;
                    int col = an * 8 + (lane & 3) * 2 + (t & 1);
                    rbase[row * 34 + col] = acc[am][an][t];
                }
    }
    __syncthreads();
    if (wk == 1) return;
    #pragma unroll
    for (int am = 0; am < 2; am++)
        #pragma unroll
        for (int an = 0; an < 4; an++)
            #pragma unroll
            for (int t = 0; t < 4; t++) {
                int row = am * 16 + (lane >> 2) + (t >> 1) * 8;
                int col = an * 8 + (lane & 3) * 2 + (t & 1);
                acc[am][an][t] += rbase[row * 34 + col];
            }

    // ---- epilogue (wk=0 warps only): registers -> global ----
    #pragma unroll
    for (int am = 0; am < 2; am++) {
        #pragma unroll
        for (int an = 0; an < 4; an++) {
            int m0 = mBase + wm * 32 + am * 16 + (lane >> 2);
            int g  = nBase + wn * 32 + an * 8 + (lane & 3) * 2;
            #pragma unroll
            for (int half = 0; half < 2; half++) {
                int m = m0 + half * 8;
                float v0 = acc[am][an][half * 2];
                float v1 = acc[am][an][half * 2 + 1];
                if (EP == 0) {                          // relu -> fp16
                    v0 = fmaxf(v0 + biasP[g], 0.f);
                    v1 = fmaxf(v1 + biasP[g + 1], 0.f);
                    store_h2(oH, (size_t)m * HIDDEN + g, v0, v1);
                } else if (EP == 1) {                   // xsub fp32
                    v0 += biasP[g]; v1 += biasP[g + 1];
                    *(float2*)(o32 + (size_t)m * HIDDEN + g) = make_float2(v0, v1);
                } else if (EP == 2) {                   // qkv split fp16
                    int which = g >> 9, lc = g & 511;
                    const float* bb = (which == 0) ? bq : (which == 1) ? bk : bv;
                    __half* dst = (which == 0) ? oq : (which == 1) ? okk : ov;
                    v0 += bb[lc]; v1 += bb[lc + 1];
                    store_h2(dst, (size_t)m * HIDDEN + lc, v0, v1);
                } else if (EP == 3) {                   // fp16 out (t)
                    v0 += biasP[g]; v1 += biasP[g + 1];
                    store_h2(oH, (size_t)m * HIDDEN + g, v0, v1);
                } else {                                // out = . + bp + xsub, (b,s) order
                    v0 += biasP[g] + resid[(size_t)m * HIDDEN + g];
                    v1 += biasP[g + 1] + resid[(size_t)m * HIDDEN + g + 1];
                    int bb2 = m & (BATCH - 1), ss = m >> 8;
                    *(float2*)(o32 + ((size_t)((bb2 << 3) + ss)) * HIDDEN + g) = make_float2(v0, v1);
                }
            }
        }
    }
}

// ---------------- LayerNorm: one warp per row, xsub fp32 -> xn fp16 ----------------
__global__ __launch_bounds__(256) void ln_kernel(const float* __restrict__ lng,
                                                 const float* __restrict__ lnb)
{
    int gw = (blockIdx.x * 256 + threadIdx.x) >> 5;   // global warp = row
    int l  = threadIdx.x & 31;
    if (gw >= ROWS) return;
    const float* xs = g_xsub + (size_t)gw * HIDDEN;

    float4 v[4];
    #pragma unroll
    for (int i = 0; i < 4; i++)
        v[i] = *(const float4*)(xs + l * 4 + i * 128);

    float s = 0.f, q = 0.f;
    #pragma unroll
    for (int i = 0; i < 4; i++) {
        s += v[i].x + v[i].y + v[i].z + v[i].w;
        q += v[i].x * v[i].x + v[i].y * v[i].y + v[i].z * v[i].z + v[i].w * v[i].w;
    }
    #pragma unroll
    for (int o = 16; o > 0; o >>= 1) {
        s += __shfl_xor_sync(0xFFFFFFFFu, s, o);
        q += __shfl_xor_sync(0xFFFFFFFFu, q, o);
    }
    float mean = s * (1.f / HIDDEN);
    float var  = q * (1.f / HIDDEN) - mean * mean;
    float inv  = rsqrtf(var + LN_EPS);

    __half* outp = g_xn + (size_t)gw * HIDDEN;
    #pragma unroll
    for (int i = 0; i < 4; i++) {
        int c = l * 4 + i * 128;
        float o0 = (v[i].x - mean) * inv * lng[c]     + lnb[c];
        float o1 = (v[i].y - mean) * inv * lng[c + 1] + lnb[c + 1];
        float o2 = (v[i].z - mean) * inv * lng[c + 2] + lnb[c + 2];
        float o3 = (v[i].w - mean) * inv * lng[c + 3] + lnb[c + 3];
        H4 hv;
        hv.p[0] = __floats2half2_rn(o0, o1);
        hv.p[1] = __floats2half2_rn(o2, o3);
        *(uint2*)(outp + c) = hv.u;
    }
}

// ---------------- attention: q,k,v fp16 -> ctx fp16 ----------------
__global__ __launch_bounds__(256) void attn_kernel()
{
    __shared__ float q_s[NUM_SUBNETS][520];
    __shared__ float k_s[NUM_SUBNETS][520];
    __shared__ float sc[HEADS][NUM_SUBNETS][NUM_SUBNETS];

    int b = blockIdx.x;
    int tid = threadIdx.x;

    for (int i = tid; i < NUM_SUBNETS * HIDDEN; i += 256) {
        int m = i >> 9, c = i & 511;
        size_t gi = ((size_t)(m * BATCH + b)) * HIDDEN + c;
        q_s[m][c] = __half2float(g_q[gi]);
        k_s[m][c] = __half2float(g_k[gi]);
    }
    __syncthreads();

    int h = tid >> 5, l = tid & 31;

    #pragma unroll
    for (int pp = 0; pp < 2; pp++) {
        int p = l + pp * 32;
        int m = p >> 3, n = p & 7;
        const float* qp = &q_s[m][h * HEAD_DIM];
        const float* kp = &k_s[n][h * HEAD_DIM];
        float sv = 0.f;
        #pragma unroll
        for (int d = 0; d < HEAD_DIM; d++) sv += qp[d] * kp[d];
        sv *= 0.125f;
        sc[h][m][n] = (m == n) ? 0.f : sv;
    }
    __syncwarp();

    if (l < NUM_SUBNETS) {
        float mx = -1e30f;
        #pragma unroll
        for (int n = 0; n < 8; n++) mx = fmaxf(mx, sc[h][l][n]);
        float e[8], sum = 0.f;
        #pragma unroll
        for (int n = 0; n < 8; n++) { e[n] = expf(sc[h][l][n] - mx); sum += e[n]; }
        float inv = 1.f / sum;
        #pragma unroll
        for (int n = 0; n < 8; n++) sc[h][l][n] = e[n] * inv;
    }
    __syncwarp();

    #pragma unroll
    for (int dd = 0; dd < 2; dd++) {
        int d = l + dd * 32;
        float vv[8];
        #pragma unroll
        for (int n = 0; n < 8; n++)
            vv[n] = __half2float(g_v[((size_t)(n * BATCH + b)) * HIDDEN + h * HEAD_DIM + d]);
        #pragma unroll
        for (int m = 0; m < 8; m++) {
            float cv = 0.f;
            #pragma unroll
            for (int n = 0; n < 8; n++) cv += sc[h][m][n] * vv[n];
            g_ctx[((size_t)(m * BATCH + b)) * HIDDEN + h * HEAD_DIM + d] = __float2half_rn(cv);
        }
    }
}

// ---------------- launch ----------------
extern "C" void kernel_launch(void* const* d_in, const int* in_sizes, int n_in,
                              void* d_out, int out_size)
{
    (void)in_sizes; (void)n_in; (void)out_size;
    const float* x    = (const float*)d_in[0];
    const float* W1   = (const float*)d_in[2];
    const float* b1   = (const float*)d_in[3];
    const float* W2   = (const float*)d_in[4];
    const float* b2   = (const float*)d_in[5];
    const float* ln_g = (const float*)d_in[6];
    const float* ln_b = (const float*)d_in[7];
    const float* Wq   = (const float*)d_in[8];
    const float* bq   = (const float*)d_in[9];
    const float* Wk   = (const float*)d_in[10];
    const float* bk   = (const float*)d_in[11];
    const float* Wv   = (const float*)d_in[12];
    const float* bv   = (const float*)d_in[13];
    const float* Wo   = (const float*)d_in[14];
    const float* bo   = (const float*)d_in[15];
    const float* Wp   = (const float*)d_in[16];
    const float* bp   = (const float*)d_in[17];
    float* out = (float*)d_out;

    __half *flat, *W1T_hi, *W2T_hi, *WqkvT_hi, *WoT_hi, *WpT_hi;
    __half *h, *xn, *ctx, *t, *pq, *pk, *pv;
    float *xsub;
    cudaGetSymbolAddress((void**)&flat,    g_flat);
    cudaGetSymbolAddress((void**)&W1T_hi,  g_W1T_hi);
    cudaGetSymbolAddress((void**)&W2T_hi,  g_W2T_hi);
    cudaGetSymbolAddress((void**)&WqkvT_hi, g_WqkvT_hi);
    cudaGetSymbolAddress((void**)&WoT_hi,  g_WoT_hi);
    cudaGetSymbolAddress((void**)&WpT_hi,  g_WpT_hi);
    cudaGetSymbolAddress((void**)&h,       g_h);
    cudaGetSymbolAddress((void**)&xn,      g_xn);
    cudaGetSymbolAddress((void**)&ctx,     g_ctx);
    cudaGetSymbolAddress((void**)&t,       g_t);
    cudaGetSymbolAddress((void**)&xsub,    g_xsub);
    cudaGetSymbolAddress((void**)&pq,      g_q);
    cudaGetSymbolAddress((void**)&pk,      g_k);
    cudaGetSymbolAddress((void**)&pv,      g_v);

    const int SMEM1  = 4 * 2 * T_BYTES;   // OCC=2: 73728
    const int SMEMQ  = 3 * 2 * T_BYTES;   // OCC=3: 55296
    cudaFuncSetAttribute((const void*)tc_gemm<0,2>, cudaFuncAttributeMaxDynamicSharedMemorySize, SMEM1);
    cudaFuncSetAttribute((const void*)tc_gemm<1,2>, cudaFuncAttributeMaxDynamicSharedMemorySize, SMEM1);
    cudaFuncSetAttribute((const void*)tc_gemm<2,3>, cudaFuncAttributeMaxDynamicSharedMemorySize, SMEMQ);
    cudaFuncSetAttribute((const void*)tc_gemm<3,2>, cudaFuncAttributeMaxDynamicSharedMemorySize, SMEM1);
    cudaFuncSetAttribute((const void*)tc_gemm<4,2>, cudaFuncAttributeMaxDynamicSharedMemorySize, SMEM1);

    // ---- all input conversions in ONE launch ----
    W13 wa;
    for (int z = 0; z < 8; z++) {
        wa.src[z] = W2 + (size_t)z * HIDDEN * HIDDEN;
        wa.dhi[z] = W2T_hi + (size_t)z * HIDDEN * HIDDEN;
    }
    const float* srcs[5] = { Wq, Wk, Wv, Wo, Wp };
    __half* dhis[5] = { WqkvT_hi, WqkvT_hi + 512 * 512, WqkvT_hi + 1024 * 512, WoT_hi, WpT_hi };
    for (int z = 0; z < 5; z++) {
        wa.src[8 + z] = srcs[z];
        wa.dhi[8 + z] = dhis[z];
    }
    convert_all_kernel<<<NB_ALL, 256>>>(x, W1, wa);

    dim3 g512(HIDDEN / BN, ROWS / BM);        // 8 x 32 = 256 CTAs
    dim3 gqkv(3 * HIDDEN / BN, ROWS / BM);    // 24 x 32 = 768 CTAs

    // GEMM1: h = relu(flat @ W1 + b1) -> fp16
    tc_gemm<0,2><<<g512, 256, SMEM1>>>(flat, KPAD1, W1T_hi, KPAD1,
        (long)HIDDEN * KPAD1, KPAD1 / BK, b1, nullptr, h,
        nullptr, nullptr, nullptr, nullptr, nullptr, nullptr, nullptr);
    // GEMM2: xsub = h @ W2 + b2 (fp32 out)
    tc_gemm<1,2><<<g512, 256, SMEM1>>>(h, HIDDEN, W2T_hi, HIDDEN,
        (long)HIDDEN * HIDDEN, HIDDEN / BK, b2, xsub, nullptr,
        nullptr, nullptr, nullptr, nullptr, nullptr, nullptr, nullptr);
    // LN -> xn fp16 (one warp per row)
    ln_kernel<<<ROWS / 8, 256>>>(ln_g, ln_b);
    // QKV fused (fp16 outputs, 3 CTAs/SM)
    tc_gemm<2,3><<<gqkv, 256, SMEMQ>>>(xn, HIDDEN, WqkvT_hi, HIDDEN,
        0L, HIDDEN / BK, nullptr, nullptr, nullptr,
        nullptr, pq, pk, pv, bq, bk, bv);
    // attention -> ctx fp16
    attn_kernel<<<BATCH, 256>>>();
    // O: t = ctx @ Wo + bo -> fp16
    tc_gemm<3,2><<<g512, 256, SMEM1>>>(ctx, HIDDEN, WoT_hi, HIDDEN,
        0L, HIDDEN / BK, bo, nullptr, t,
        nullptr, nullptr, nullptr, nullptr, nullptr, nullptr, nullptr);
    // P: out = t @ Wp + bp + xsub (permuted to (b,s))
    tc_gemm<4,2><<<g512, 256, SMEM1>>>(t, HIDDEN, WpT_hi, HIDDEN,
        0L, HIDDEN / BK, bp, out, nullptr,
        xsub, nullptr, nullptr, nullptr, nullptr, nullptr, nullptr);
}